// round 2
// baseline (speedup 1.0000x reference)
#include <cuda_runtime.h>

#define Lq 128
#define Bb 8
#define Hh 16
#define HDv 64
#define Dm 1024

// Scratch (no allocations allowed)
__device__ float g_Cq[Dm * Dm];     // new_q = query@Wq^T + e0 bias, laid out (L*B, D)
__device__ float g_Ck[Dm * Dm];
__device__ float g_Cv[Dm * Dm];
__device__ float g_AO[Dm * Dm];     // attention output, (L*B, D)
__device__ float g_Ghat[Dm * 16];   // [k][hs]
__device__ float g_dbuf[Dm * 16];   // [rr][hs]

// ---------------------------------------------------------------------------
// GEMM: C[1024][1024] = A[1024][1024] @ W^T (+ bias[n] if bias != nullptr)
// BM=128, BN=64, BK=16, 256 threads, 8x4 microtile. Conflict-free frag loads.
// ---------------------------------------------------------------------------
__global__ __launch_bounds__(256) void gemm_xwT(const float* __restrict__ A,
                                                const float* __restrict__ W,
                                                float* __restrict__ C,
                                                const float* __restrict__ bias) {
    __shared__ float As[16][128];
    __shared__ float Ws[16][64];
    const int m0 = blockIdx.y * 128;
    const int n0 = blockIdx.x * 64;
    const int tid = threadIdx.x;
    const int mi = (tid >> 4) * 8;  // 0..120
    const int nj = (tid & 15) * 4;  // 0..60

    float acc[8][4];
#pragma unroll
    for (int i = 0; i < 8; i++)
#pragma unroll
        for (int j = 0; j < 4; j++) acc[i][j] = 0.f;

    for (int k0 = 0; k0 < 1024; k0 += 16) {
#pragma unroll
        for (int t = 0; t < 2; t++) {
            int f = tid + t * 256;
            int m = f >> 2, kq = (f & 3) << 2;
            float4 v = *(const float4*)(A + (size_t)(m0 + m) * 1024 + k0 + kq);
            As[kq + 0][m] = v.x; As[kq + 1][m] = v.y;
            As[kq + 2][m] = v.z; As[kq + 3][m] = v.w;
        }
        {
            int m = tid >> 2, kq = (tid & 3) << 2;
            float4 v = *(const float4*)(W + (size_t)(n0 + m) * 1024 + k0 + kq);
            Ws[kq + 0][m] = v.x; Ws[kq + 1][m] = v.y;
            Ws[kq + 2][m] = v.z; Ws[kq + 3][m] = v.w;
        }
        __syncthreads();
#pragma unroll
        for (int kk = 0; kk < 16; kk++) {
            float4 a0 = *(const float4*)&As[kk][mi];
            float4 a1 = *(const float4*)&As[kk][mi + 4];
            float4 bv = *(const float4*)&Ws[kk][nj];
            float av[8] = {a0.x, a0.y, a0.z, a0.w, a1.x, a1.y, a1.z, a1.w};
            float bw[4] = {bv.x, bv.y, bv.z, bv.w};
#pragma unroll
            for (int ii = 0; ii < 8; ii++)
#pragma unroll
                for (int jj = 0; jj < 4; jj++)
                    acc[ii][jj] = fmaf(av[ii], bw[jj], acc[ii][jj]);
        }
        __syncthreads();
    }
    float4 badd = make_float4(0.f, 0.f, 0.f, 0.f);
    if (bias) badd = *(const float4*)(bias + n0 + nj);
#pragma unroll
    for (int ii = 0; ii < 8; ii++) {
        float4 o;
        o.x = acc[ii][0] + badd.x;
        o.y = acc[ii][1] + badd.y;
        o.z = acc[ii][2] + badd.z;
        o.w = acc[ii][3] + badd.w;
        *(float4*)(C + (size_t)(m0 + mi + ii) * 1024 + n0 + nj) = o;
    }
}

// ---------------------------------------------------------------------------
// Ghat[k][hs] = sum_{c<64} Wr[hs*64+c][k] * e0[hs*64+c]
// Replaces the full Wr projection GEMM (a3 only ever sees e0 . r).
// ---------------------------------------------------------------------------
__global__ __launch_bounds__(256) void ghat_kernel(const float* __restrict__ Wr,
                                                   const float* __restrict__ spk_emb) {
    int idx = blockIdx.x * 256 + threadIdx.x;  // 16384 total
    int hs = idx >> 10;
    int k = idx & 1023;
    float s = 0.f;
#pragma unroll 8
    for (int c = 0; c < 64; c++)
        s = fmaf(Wr[(size_t)(hs * 64 + c) * 1024 + k], spk_emb[hs * 64 + c], s);
    g_Ghat[k * 16 + hs] = s;
}

// d[rr][hs] = rel_pe_2d[rr,:] @ Ghat[:,hs]   (1024 x 1024 x 16)
__global__ __launch_bounds__(256) void dmat_kernel(const float* __restrict__ relpe) {
    int hs = threadIdx.x & 15;
    int rr = blockIdx.x * 16 + (threadIdx.x >> 4);
    const float* arow = relpe + (size_t)rr * 1024;
    float s = 0.f;
    for (int k = 0; k < 1024; k += 4) {
        float4 a = *(const float4*)(arow + k);
        s = fmaf(a.x, g_Ghat[(k + 0) * 16 + hs], s);
        s = fmaf(a.y, g_Ghat[(k + 1) * 16 + hs], s);
        s = fmaf(a.z, g_Ghat[(k + 2) * 16 + hs], s);
        s = fmaf(a.w, g_Ghat[(k + 3) * 16 + hs], s);
    }
    g_dbuf[rr * 16 + hs] = s;
}

// ---------------------------------------------------------------------------
// Fused attention per (b, h): scores = (newQ.K^T + a2 + a3)*SCALE with causal
// handling -> masked entries = 1e-30 exactly (ref uses where(mask,1e-30,s)),
// softmax over all 128 j, then P @ V into g_AO.
// ---------------------------------------------------------------------------
// smem float offsets
#define QS_OFF 0
#define KS_OFF 8320
#define VS_OFF 16640
#define S_OFF 24960
#define E0_OFF 41472
#define E1_OFF 41536
#define CV_OFF 41600
#define SD0_OFF 41728
#define SD1_OFF 41856
#define ATTN_SMEM_FLOATS 41984
#define ATTN_SMEM_BYTES (ATTN_SMEM_FLOATS * 4)

__global__ __launch_bounds__(256) void attn_kernel(const int* __restrict__ spk_mask,
                                                   const float* __restrict__ spk_emb) {
    extern __shared__ float sm[];
    float* Qs = sm + QS_OFF;    // [128][65]
    float* Ks = sm + KS_OFF;    // [128][65]
    float* Vs = sm + VS_OFF;    // [128][65]
    float* S = sm + S_OFF;      // [128][129]
    float* e0h = sm + E0_OFF;   // [64]
    float* e1h = sm + E1_OFF;   // [64]
    float* cvec = sm + CV_OFF;  // [128]
    float* sd0 = sm + SD0_OFF;  // [128]
    float* sd1 = sm + SD1_OFF;  // [128]

    const int b = blockIdx.x, h = blockIdx.y;
    const int tid = threadIdx.x;

    // stage Q/K/V head tiles (row i of head = g_C*[ (i*8+b)*1024 + h*64 + hd ])
    for (int idx = tid; idx < 128 * 64; idx += 256) {
        int i = idx >> 6, hd = idx & 63;
        size_t g = (size_t)(i * 8 + b) * 1024 + h * 64 + hd;
        Qs[i * 65 + hd] = g_Cq[g];
        Ks[i * 65 + hd] = g_Ck[g];
        Vs[i * 65 + hd] = g_Cv[g];
    }
    if (tid < 64) {
        e0h[tid] = spk_emb[h * 64 + tid];
        e1h[tid] = spk_emb[1024 + h * 64 + tid];
    } else if (tid < 192) {
        int j = tid - 64;
        cvec[j] = g_dbuf[(j * 8 + b) * 16 + h];  // c[n, j]
    }
    __syncthreads();

    // per-row speaker dots: sd_e[i] = new_q[i] . spk_emb[e, head slice]
    if (tid < 128) {
        float s0 = 0.f, s1 = 0.f;
        const float* qrow = Qs + tid * 65;
#pragma unroll
        for (int k = 0; k < 64; k++) {
            float q = qrow[k];
            s0 = fmaf(q, e0h[k], s0);
            s1 = fmaf(q, e1h[k], s1);
        }
        sd0[tid] = s0;
        sd1[tid] = s1;
    }
    __syncthreads();

    // scores: 8x8 microtile per thread, interleaved i = ti+16*ii, j = tj+16*jj
    // (interleaving keeps the stride-65 Ks reads conflict-free: 65 mod 32 = 1)
    const int ti = tid >> 4, tj = tid & 15;
    float acc[8][8];
#pragma unroll
    for (int a = 0; a < 8; a++)
#pragma unroll
        for (int c2 = 0; c2 < 8; c2++) acc[a][c2] = 0.f;
    for (int k = 0; k < 64; k++) {
        float qa[8], kb[8];
#pragma unroll
        for (int ii = 0; ii < 8; ii++) qa[ii] = Qs[(ti + 16 * ii) * 65 + k];
#pragma unroll
        for (int jj = 0; jj < 8; jj++) kb[jj] = Ks[(tj + 16 * jj) * 65 + k];
#pragma unroll
        for (int ii = 0; ii < 8; ii++)
#pragma unroll
            for (int jj = 0; jj < 8; jj++)
                acc[ii][jj] = fmaf(qa[ii], kb[jj], acc[ii][jj]);
    }
    const int* spm = spk_mask + b * 128 * 128;
#pragma unroll
    for (int ii = 0; ii < 8; ii++) {
        int i = ti + 16 * ii;
#pragma unroll
        for (int jj = 0; jj < 8; jj++) {
            int j = tj + 16 * jj;
            float v;
            if (j <= i) {
                float a2 = spm[i * 128 + j] ? sd1[i] : sd0[i];
                float a3 = cvec[127 - i + j];  // rel_shift closed form
                v = (acc[ii][jj] + a2 + a3) * 0.125f;
            } else {
                v = 1e-30f;  // reference: where(mask, 1e-30, scores)
            }
            S[i * 129 + j] = v;
        }
    }
    __syncthreads();

    // softmax per row (128 rows, thread-per-row)
    if (tid < 128) {
        float* row = S + tid * 129;
        float mx = row[0];
        for (int j = 1; j < 128; j++) mx = fmaxf(mx, row[j]);
        float sum = 0.f;
        for (int j = 0; j < 128; j++) {
            float e = __expf(row[j] - mx);
            row[j] = e;
            sum += e;
        }
        float inv = 1.f / sum;
        for (int j = 0; j < 128; j++) row[j] *= inv;
    }
    __syncthreads();

    // out = P @ V  (128x64), 4x8 microtile per thread
    const int r = tid >> 3, c = tid & 7;
    float oacc[4][8];
#pragma unroll
    for (int a = 0; a < 4; a++)
#pragma unroll
        for (int c2 = 0; c2 < 8; c2++) oacc[a][c2] = 0.f;
    for (int j = 0; j < 128; j++) {
        float wv[4], vv[8];
#pragma unroll
        for (int ii = 0; ii < 4; ii++) wv[ii] = S[(r + 32 * ii) * 129 + j];
#pragma unroll
        for (int jj = 0; jj < 8; jj++) vv[jj] = Vs[j * 65 + c + 8 * jj];
#pragma unroll
        for (int ii = 0; ii < 4; ii++)
#pragma unroll
            for (int jj = 0; jj < 8; jj++)
                oacc[ii][jj] = fmaf(wv[ii], vv[jj], oacc[ii][jj]);
    }
#pragma unroll
    for (int ii = 0; ii < 4; ii++) {
        int i = r + 32 * ii;
#pragma unroll
        for (int jj = 0; jj < 8; jj++) {
            int hd = c + 8 * jj;
            g_AO[(size_t)(i * 8 + b) * 1024 + h * 64 + hd] = oacc[ii][jj];
        }
    }
}

// ---------------------------------------------------------------------------
extern "C" void kernel_launch(void* const* d_in, const int* in_sizes, int n_in,
                              void* d_out, int out_size) {
    // metadata order: query, rel_pe, utt_mask, Wq, Wk, Wv, Wr, Wo, spk_emb,
    //                 attn_mask, spk_mask  (utt_mask/attn_mask are causal ->
    //                 recomputed inline, not read)
    const float* query = (const float*)d_in[0];
    const float* rel_pe = (const float*)d_in[1];
    const float* Wq = (const float*)d_in[3];
    const float* Wk = (const float*)d_in[4];
    const float* Wv = (const float*)d_in[5];
    const float* Wr = (const float*)d_in[6];
    const float* Wo = (const float*)d_in[7];
    const float* spk_emb = (const float*)d_in[8];
    const int* spk_mask = (const int*)d_in[10];
    float* out = (float*)d_out;

    void *pCq, *pCk, *pCv, *pAO;
    cudaGetSymbolAddress(&pCq, g_Cq);
    cudaGetSymbolAddress(&pCk, g_Ck);
    cudaGetSymbolAddress(&pCv, g_Cv);
    cudaGetSymbolAddress(&pAO, g_AO);

    cudaFuncSetAttribute(attn_kernel, cudaFuncAttributeMaxDynamicSharedMemorySize,
                         ATTN_SMEM_BYTES);

    dim3 gg(16, 8);  // N-blocks x M-blocks
    // new_q = query @ Wq^T + e0 (bias fused; spk_emb row 0 is the bias vector)
    gemm_xwT<<<gg, 256>>>(query, Wq, (float*)pCq, spk_emb);
    gemm_xwT<<<gg, 256>>>(query, Wk, (float*)pCk, nullptr);
    gemm_xwT<<<gg, 256>>>(query, Wv, (float*)pCv, nullptr);
    ghat_kernel<<<64, 256>>>(Wr, spk_emb);
    dmat_kernel<<<64, 256>>>(rel_pe);
    attn_kernel<<<dim3(8, 16), 256, ATTN_SMEM_BYTES>>>(spk_mask, spk_emb);
    gemm_xwT<<<gg, 256>>>((const float*)pAO, Wo, out, nullptr);
}

// round 5
// speedup vs baseline: 1.9231x; 1.9231x over previous
#include <cuda_runtime.h>
#include <cstdint>

#define Lq 128
#define Bb 8
#define Hh 16
#define HDv 64
#define Dm 1024

// Scratch (no allocations allowed)
__device__ float g_Cq[Dm * Dm];     // new_q = query@Wq^T + e0 bias, laid out (L*B, D)
__device__ float g_Ck[Dm * Dm];
__device__ float g_Cv[Dm * Dm];
__device__ float g_AO[Dm * Dm];     // attention output, (L*B, D)
__device__ float g_Ghat[Dm * 16];   // [k][hs]
__device__ float g_dbuf[Dm * 16];   // [rr][hs]

__device__ __forceinline__ void cp_async16(uint32_t s, const void* g) {
    asm volatile("cp.async.cg.shared.global [%0], [%1], 16;" :: "r"(s), "l"(g));
}
__device__ __forceinline__ uint32_t smem_u32(const void* p) {
    uint32_t a;
    asm("{ .reg .u64 t; cvta.to.shared.u64 t, %1; cvt.u32.u64 %0, t; }" : "=r"(a) : "l"(p));
    return a;
}
__device__ __forceinline__ void mma_tf32(float* c, uint32_t a0, uint32_t a1,
                                         uint32_t a2, uint32_t a3,
                                         uint32_t b0, uint32_t b1) {
    asm volatile(
        "mma.sync.aligned.m16n8k8.row.col.f32.tf32.tf32.f32 "
        "{%0,%1,%2,%3}, {%4,%5,%6,%7}, {%8,%9}, {%0,%1,%2,%3};"
        : "+f"(c[0]), "+f"(c[1]), "+f"(c[2]), "+f"(c[3])
        : "r"(a0), "r"(a1), "r"(a2), "r"(a3), "r"(b0), "r"(b1));
}
// round-to-nearest tf32 head; returns fp32 bit pattern with low 13 bits cleared
__device__ __forceinline__ uint32_t tf32_hi(float x) {
    uint32_t r;
    asm("cvt.rna.tf32.f32 %0, %1;" : "=r"(r) : "f"(x));
    return r;
}

// ---------------------------------------------------------------------------
// 3xTF32 mma.sync GEMM: C[1024][1024] = A @ W^T (+ bias), fp32-accurate.
// BM=128, BN=64, BK=32, 256 threads (8 warps, 4x2), warp tile 32x32.
// cp.async double-buffered. Smem rows padded to 36 floats (conflict-free).
// Each logical MMA = hi*hi + hi*lo + lo*hi (lo*lo term ~2^-22, dropped).
// ---------------------------------------------------------------------------
#define APAD 36
#define A_TILE_F (128 * APAD)
#define B_TILE_F (64 * APAD)
#define GSM_A0 0
#define GSM_A1 A_TILE_F
#define GSM_B0 (2 * A_TILE_F)
#define GSM_B1 (2 * A_TILE_F + B_TILE_F)
#define GEMM_SMEM_FLOATS (2 * A_TILE_F + 2 * B_TILE_F)
#define GEMM_SMEM_BYTES (GEMM_SMEM_FLOATS * 4)

__global__ __launch_bounds__(256) void gemm_mma(const float* __restrict__ A,
                                                const float* __restrict__ W,
                                                float* __restrict__ C,
                                                const float* __restrict__ bias) {
    extern __shared__ float sm[];
    const int tid = threadIdx.x;
    const int wid = tid >> 5, lane = tid & 31;
    const int g = lane >> 2, tg = lane & 3;
    const int wm = wid >> 1, wn = wid & 1;  // warp grid 4(M) x 2(N)
    const int m0 = blockIdx.y * 128, n0 = blockIdx.x * 64;

    float* sA[2] = {sm + GSM_A0, sm + GSM_A1};
    float* sB[2] = {sm + GSM_B0, sm + GSM_B1};
    const uint32_t sAa[2] = {smem_u32(sA[0]), smem_u32(sA[1])};
    const uint32_t sBa[2] = {smem_u32(sB[0]), smem_u32(sB[1])};

    float acc[2][4][4];
#pragma unroll
    for (int mt = 0; mt < 2; mt++)
#pragma unroll
        for (int nt = 0; nt < 4; nt++)
#pragma unroll
            for (int r = 0; r < 4; r++) acc[mt][nt][r] = 0.f;

    auto load_tiles = [&](int buf, int k0) {
#pragma unroll
        for (int i = 0; i < 4; i++) {  // A: 1024 16B chunks
            int q = tid + (i << 8);
            int row = q >> 3, c16 = q & 7;
            cp_async16(sAa[buf] + (uint32_t)(row * APAD + c16 * 4) * 4,
                       A + (size_t)(m0 + row) * 1024 + k0 + (c16 << 2));
        }
#pragma unroll
        for (int i = 0; i < 2; i++) {  // B: 512 16B chunks
            int q = tid + (i << 8);
            int row = q >> 3, c16 = q & 7;
            cp_async16(sBa[buf] + (uint32_t)(row * APAD + c16 * 4) * 4,
                       W + (size_t)(n0 + row) * 1024 + k0 + (c16 << 2));
        }
        asm volatile("cp.async.commit_group;");
    };

    load_tiles(0, 0);

    for (int it = 0; it < 32; ++it) {
        const int cur = it & 1;
        if (it + 1 < 32) {
            load_tiles(cur ^ 1, (it + 1) * 32);
            asm volatile("cp.async.wait_group 1;");
        } else {
            asm volatile("cp.async.wait_group 0;");
        }
        __syncthreads();

        const float* As = sA[cur];
        const float* Bs = sB[cur];
#pragma unroll
        for (int ks = 0; ks < 4; ks++) {
            const int k0 = ks * 8;
            uint32_t ah[2][4], al[2][4];
#pragma unroll
            for (int mt = 0; mt < 2; mt++) {
                const float* ar0 = As + (wm * 32 + mt * 16 + g) * APAD + k0;
                const float* ar1 = ar0 + 8 * APAD;
                float av[4] = {ar0[tg], ar1[tg], ar0[tg + 4], ar1[tg + 4]};
#pragma unroll
                for (int r = 0; r < 4; r++) {
                    uint32_t hb = tf32_hi(av[r]);
                    ah[mt][r] = hb;
                    al[mt][r] = __float_as_uint(av[r] - __uint_as_float(hb));
                }
            }
#pragma unroll
            for (int nt = 0; nt < 4; nt++) {
                const float* br = Bs + (wn * 32 + nt * 8 + g) * APAD + k0;
                float b0f = br[tg], b1f = br[tg + 4];
                uint32_t bh0 = tf32_hi(b0f), bh1 = tf32_hi(b1f);
                uint32_t bl0 = __float_as_uint(b0f - __uint_as_float(bh0));
                uint32_t bl1 = __float_as_uint(b1f - __uint_as_float(bh1));
#pragma unroll
                for (int mt = 0; mt < 2; mt++) {
                    mma_tf32(acc[mt][nt], ah[mt][0], ah[mt][1], ah[mt][2], ah[mt][3],
                             bh0, bh1);
                    mma_tf32(acc[mt][nt], ah[mt][0], ah[mt][1], ah[mt][2], ah[mt][3],
                             bl0, bl1);
                    mma_tf32(acc[mt][nt], al[mt][0], al[mt][1], al[mt][2], al[mt][3],
                             bh0, bh1);
                }
            }
        }
        __syncthreads();
    }

    // epilogue: direct float2 stores (+ bias)
#pragma unroll
    for (int mt = 0; mt < 2; mt++) {
        const int r0 = m0 + wm * 32 + mt * 16 + g;
#pragma unroll
        for (int nt = 0; nt < 4; nt++) {
            const int col = n0 + wn * 32 + nt * 8 + tg * 2;
            float bx = 0.f, by = 0.f;
            if (bias) {
                bx = bias[col];
                by = bias[col + 1];
            }
            float2 v0 = make_float2(acc[mt][nt][0] + bx, acc[mt][nt][1] + by);
            float2 v1 = make_float2(acc[mt][nt][2] + bx, acc[mt][nt][3] + by);
            *(float2*)(C + (size_t)r0 * 1024 + col) = v0;
            *(float2*)(C + (size_t)(r0 + 8) * 1024 + col) = v1;
        }
    }
}

// ---------------------------------------------------------------------------
// Ghat[k][hs] = sum_{c<64} Wr[hs*64+c][k] * e0[hs*64+c]
// ---------------------------------------------------------------------------
__global__ __launch_bounds__(256) void ghat_kernel(const float* __restrict__ Wr,
                                                   const float* __restrict__ spk_emb) {
    __shared__ float part[128];
    const int kc = blockIdx.x;
    const int hs = blockIdx.y;
    const int kk = threadIdx.x & 127;
    const int ch = threadIdx.x >> 7;
    const float* base = Wr + (size_t)(hs * 64 + ch * 32) * 1024 + kc * 128 + kk;
    float s = 0.f;
#pragma unroll
    for (int c2 = 0; c2 < 32; c2++)
        s = fmaf(base[(size_t)c2 * 1024], spk_emb[hs * 64 + ch * 32 + c2], s);
    if (ch) part[kk] = s;
    __syncthreads();
    if (!ch) g_Ghat[(kc * 128 + kk) * 16 + hs] = s + part[kk];
}

// d[rr][hs] = rel_pe_2d[rr,:] @ Ghat[:,hs]
__global__ __launch_bounds__(128) void dmat_kernel(const float* __restrict__ relpe) {
    __shared__ float gh[2048];
    const int rrl = threadIdx.x >> 4, hs = threadIdx.x & 15;
    const int rr = blockIdx.x * 8 + rrl;
    float acc = 0.f;
    for (int chk = 0; chk < 8; chk++) {
        for (int i = threadIdx.x; i < 2048; i += 128) gh[i] = g_Ghat[chk * 2048 + i];
        __syncthreads();
        const float4* arow = (const float4*)(relpe + (size_t)rr * 1024 + chk * 128);
#pragma unroll
        for (int k4 = 0; k4 < 32; k4++) {
            float4 a = arow[k4];
            acc = fmaf(a.x, gh[(k4 * 4 + 0) * 16 + hs], acc);
            acc = fmaf(a.y, gh[(k4 * 4 + 1) * 16 + hs], acc);
            acc = fmaf(a.z, gh[(k4 * 4 + 2) * 16 + hs], acc);
            acc = fmaf(a.w, gh[(k4 * 4 + 3) * 16 + hs], acc);
        }
        __syncthreads();
    }
    g_dbuf[rr * 16 + hs] = acc;
}

// ---------------------------------------------------------------------------
// Fused attention per (b, h)
// ---------------------------------------------------------------------------
#define QS_OFF 0
#define KS_OFF 8320
#define VS_OFF 16640
#define S_OFF 24960
#define E0_OFF 41472
#define E1_OFF 41536
#define CV_OFF 41600
#define SD0_OFF 41728
#define SD1_OFF 41856
#define ATTN_SMEM_FLOATS 41984
#define ATTN_SMEM_BYTES (ATTN_SMEM_FLOATS * 4)

__global__ __launch_bounds__(256) void attn_kernel(const int* __restrict__ spk_mask,
                                                   const float* __restrict__ spk_emb) {
    extern __shared__ float sm[];
    float* Qs = sm + QS_OFF;
    float* Ks = sm + KS_OFF;
    float* Vs = sm + VS_OFF;
    float* S = sm + S_OFF;
    float* e0h = sm + E0_OFF;
    float* e1h = sm + E1_OFF;
    float* cvec = sm + CV_OFF;
    float* sd0 = sm + SD0_OFF;
    float* sd1 = sm + SD1_OFF;

    const int b = blockIdx.x, h = blockIdx.y;
    const int tid = threadIdx.x;

    for (int idx = tid; idx < 128 * 64; idx += 256) {
        int i = idx >> 6, hd = idx & 63;
        size_t g = (size_t)(i * 8 + b) * 1024 + h * 64 + hd;
        Qs[i * 65 + hd] = g_Cq[g];
        Ks[i * 65 + hd] = g_Ck[g];
        Vs[i * 65 + hd] = g_Cv[g];
    }
    if (tid < 64) {
        e0h[tid] = spk_emb[h * 64 + tid];
        e1h[tid] = spk_emb[1024 + h * 64 + tid];
    } else if (tid < 192) {
        int j = tid - 64;
        cvec[j] = g_dbuf[(j * 8 + b) * 16 + h];
    }
    __syncthreads();

    if (tid < 128) {
        float s0 = 0.f, s1 = 0.f;
        const float* qrow = Qs + tid * 65;
#pragma unroll
        for (int k = 0; k < 64; k++) {
            float q = qrow[k];
            s0 = fmaf(q, e0h[k], s0);
            s1 = fmaf(q, e1h[k], s1);
        }
        sd0[tid] = s0;
        sd1[tid] = s1;
    }
    __syncthreads();

    const int ti = tid >> 4, tj = tid & 15;
    float acc[8][8];
#pragma unroll
    for (int a = 0; a < 8; a++)
#pragma unroll
        for (int c2 = 0; c2 < 8; c2++) acc[a][c2] = 0.f;
    for (int k = 0; k < 64; k++) {
        float qa[8], kb[8];
#pragma unroll
        for (int ii = 0; ii < 8; ii++) qa[ii] = Qs[(ti + 16 * ii) * 65 + k];
#pragma unroll
        for (int jj = 0; jj < 8; jj++) kb[jj] = Ks[(tj + 16 * jj) * 65 + k];
#pragma unroll
        for (int ii = 0; ii < 8; ii++)
#pragma unroll
            for (int jj = 0; jj < 8; jj++)
                acc[ii][jj] = fmaf(qa[ii], kb[jj], acc[ii][jj]);
    }
    const int* spm = spk_mask + b * 128 * 128;
#pragma unroll
    for (int ii = 0; ii < 8; ii++) {
        int i = ti + 16 * ii;
#pragma unroll
        for (int jj = 0; jj < 8; jj++) {
            int j = tj + 16 * jj;
            float v;
            if (j <= i) {
                float a2 = spm[i * 128 + j] ? sd1[i] : sd0[i];
                float a3 = cvec[127 - i + j];
                v = (acc[ii][jj] + a2 + a3) * 0.125f;
            } else {
                v = 1e-30f;
            }
            S[i * 129 + j] = v;
        }
    }
    __syncthreads();

    if (tid < 128) {
        float* row = S + tid * 129;
        float mx = row[0];
        for (int j = 1; j < 128; j++) mx = fmaxf(mx, row[j]);
        float sum = 0.f;
        for (int j = 0; j < 128; j++) {
            float e = __expf(row[j] - mx);
            row[j] = e;
            sum += e;
        }
        float inv = 1.f / sum;
        for (int j = 0; j < 128; j++) row[j] *= inv;
    }
    __syncthreads();

    const int r = tid >> 3, c = tid & 7;
    float oacc[4][8];
#pragma unroll
    for (int a = 0; a < 4; a++)
#pragma unroll
        for (int c2 = 0; c2 < 8; c2++) oacc[a][c2] = 0.f;
    for (int j = 0; j < 128; j++) {
        float wv[4], vv[8];
#pragma unroll
        for (int ii = 0; ii < 4; ii++) wv[ii] = S[(r + 32 * ii) * 129 + j];
#pragma unroll
        for (int jj = 0; jj < 8; jj++) vv[jj] = Vs[j * 65 + c + 8 * jj];
#pragma unroll
        for (int ii = 0; ii < 4; ii++)
#pragma unroll
            for (int jj = 0; jj < 8; jj++)
                oacc[ii][jj] = fmaf(wv[ii], vv[jj], oacc[ii][jj]);
    }
#pragma unroll
    for (int ii = 0; ii < 4; ii++) {
        int i = r + 32 * ii;
#pragma unroll
        for (int jj = 0; jj < 8; jj++) {
            int hd = c + 8 * jj;
            g_AO[(size_t)(i * 8 + b) * 1024 + h * 64 + hd] = oacc[ii][jj];
        }
    }
}

// ---------------------------------------------------------------------------
extern "C" void kernel_launch(void* const* d_in, const int* in_sizes, int n_in,
                              void* d_out, int out_size) {
    const float* query = (const float*)d_in[0];
    const float* rel_pe = (const float*)d_in[1];
    const float* Wq = (const float*)d_in[3];
    const float* Wk = (const float*)d_in[4];
    const float* Wv = (const float*)d_in[5];
    const float* Wr = (const float*)d_in[6];
    const float* Wo = (const float*)d_in[7];
    const float* spk_emb = (const float*)d_in[8];
    const int* spk_mask = (const int*)d_in[10];
    float* out = (float*)d_out;

    void *pCq, *pCk, *pCv, *pAO;
    cudaGetSymbolAddress(&pCq, g_Cq);
    cudaGetSymbolAddress(&pCk, g_Ck);
    cudaGetSymbolAddress(&pCv, g_Cv);
    cudaGetSymbolAddress(&pAO, g_AO);

    cudaFuncSetAttribute(attn_kernel, cudaFuncAttributeMaxDynamicSharedMemorySize,
                         ATTN_SMEM_BYTES);
    cudaFuncSetAttribute(gemm_mma, cudaFuncAttributeMaxDynamicSharedMemorySize,
                         GEMM_SMEM_BYTES);

    dim3 gg(16, 8);  // N-blocks x M-blocks
    gemm_mma<<<gg, 256, GEMM_SMEM_BYTES>>>(query, Wq, (float*)pCq, spk_emb);
    gemm_mma<<<gg, 256, GEMM_SMEM_BYTES>>>(query, Wk, (float*)pCk, nullptr);
    gemm_mma<<<gg, 256, GEMM_SMEM_BYTES>>>(query, Wv, (float*)pCv, nullptr);
    ghat_kernel<<<dim3(8, 16), 256>>>(Wr, spk_emb);
    dmat_kernel<<<128, 128>>>(rel_pe);
    attn_kernel<<<dim3(8, 16), 256, ATTN_SMEM_BYTES>>>(spk_mask, spk_emb);
    gemm_mma<<<gg, 256, GEMM_SMEM_BYTES>>>((const float*)pAO, Wo, out, nullptr);
}

// round 6
// speedup vs baseline: 2.7062x; 1.4072x over previous
#include <cuda_runtime.h>
#include <cuda_bf16.h>
#include <cstdint>

#define Dm 1024
#define NELEM (Dm * Dm)

// fp32 scratch
__device__ float g_Cq[NELEM];
__device__ float g_Ck[NELEM];
__device__ float g_Cv[NELEM];
__device__ float g_Ghat[Dm * 16];
__device__ float g_dbuf[Dm * 16];
// bf16 hi/lo split scratch
__device__ __nv_bfloat16 g_Ah[NELEM], g_Al[NELEM];          // query
__device__ __nv_bfloat16 g_Wh[4 * NELEM], g_Wl[4 * NELEM];  // Wq,Wk,Wv,Wo
__device__ __nv_bfloat16 g_AOh[NELEM], g_AOl[NELEM];        // attention out

__device__ __forceinline__ void cp_async16(uint32_t s, const void* g) {
    asm volatile("cp.async.cg.shared.global [%0], [%1], 16;" :: "r"(s), "l"(g));
}
__device__ __forceinline__ uint32_t smem_u32(const void* p) {
    uint32_t a;
    asm("{ .reg .u64 t; cvta.to.shared.u64 t, %1; cvt.u32.u64 %0, t; }" : "=r"(a) : "l"(p));
    return a;
}
__device__ __forceinline__ void mma_bf16(float* c, uint32_t a0, uint32_t a1,
                                         uint32_t a2, uint32_t a3,
                                         uint32_t b0, uint32_t b1) {
    asm volatile(
        "mma.sync.aligned.m16n8k16.row.col.f32.bf16.bf16.f32 "
        "{%0,%1,%2,%3}, {%4,%5,%6,%7}, {%8,%9}, {%0,%1,%2,%3};"
        : "+f"(c[0]), "+f"(c[1]), "+f"(c[2]), "+f"(c[3])
        : "r"(a0), "r"(a1), "r"(a2), "r"(a3), "r"(b0), "r"(b1));
}

// ---------------------------------------------------------------------------
// split5: fp32 -> bf16 hi/lo for query + Wq/Wk/Wv/Wo. grid (1024, 5) x 256.
// ---------------------------------------------------------------------------
__global__ __launch_bounds__(256) void split5(const float* __restrict__ q,
                                              const float* __restrict__ wq,
                                              const float* __restrict__ wk,
                                              const float* __restrict__ wv,
                                              const float* __restrict__ wo) {
    const int arr = blockIdx.y;
    const float* src = (arr == 0) ? q : (arr == 1) ? wq : (arr == 2) ? wk
                                     : (arr == 3) ? wv : wo;
    __nv_bfloat16* hi = (arr == 0) ? g_Ah : g_Wh + (size_t)(arr - 1) * NELEM;
    __nv_bfloat16* lo = (arr == 0) ? g_Al : g_Wl + (size_t)(arr - 1) * NELEM;
    const int idx = (blockIdx.x * 256 + threadIdx.x) * 4;
    float4 v = *(const float4*)(src + idx);
    ushort4 h, l;
    float f[4] = {v.x, v.y, v.z, v.w};
    unsigned short hb[4], lb[4];
#pragma unroll
    for (int i = 0; i < 4; i++) {
        __nv_bfloat16 hv = __float2bfloat16(f[i]);
        float res = f[i] - __bfloat162float(hv);
        __nv_bfloat16 lv = __float2bfloat16(res);
        hb[i] = *(unsigned short*)&hv;
        lb[i] = *(unsigned short*)&lv;
    }
    h = make_ushort4(hb[0], hb[1], hb[2], hb[3]);
    l = make_ushort4(lb[0], lb[1], lb[2], lb[3]);
    *(ushort4*)(hi + idx) = h;
    *(ushort4*)(lo + idx) = l;
}

// ---------------------------------------------------------------------------
// bf16x3 GEMM core: C[1024][1024] = A @ W^T (+ bias), ~fp32 accuracy.
// BM=128, BN=64, BK=32, 256 threads (8 warps 4x2), warp tile 32x32.
// smem rows padded to 40 bf16 (20 words) -> conflict-free LDS.32 frags.
// ---------------------------------------------------------------------------
#define RPAD 40                         // bf16 per row (row covers 32 k)
#define A_T (128 * RPAD)                // bf16 count per A tile: 5120
#define B_T (64 * RPAD)                 // 2560
// bf16 offsets
#define OF_AH0 0
#define OF_AH1 A_T
#define OF_AL0 (2 * A_T)
#define OF_AL1 (3 * A_T)
#define OF_BH0 (4 * A_T)
#define OF_BH1 (4 * A_T + B_T)
#define OF_BL0 (4 * A_T + 2 * B_T)
#define OF_BL1 (4 * A_T + 3 * B_T)
#define GEMM_SMEM_BYTES ((4 * A_T + 4 * B_T) * 2)   // 61440

__device__ __forceinline__ void gemm_core(const __nv_bfloat16* __restrict__ Ah,
                                          const __nv_bfloat16* __restrict__ Al,
                                          const __nv_bfloat16* __restrict__ Bh,
                                          const __nv_bfloat16* __restrict__ Bl,
                                          float* __restrict__ C,
                                          const float* __restrict__ bias,
                                          int m0, int n0) {
    extern __shared__ __nv_bfloat16 smb[];
    const uint32_t sb = smem_u32(smb);
    const uint32_t* smw = (const uint32_t*)smb;
    const int tid = threadIdx.x;
    const int wid = tid >> 5, lane = tid & 31;
    const int g = lane >> 2, tg = lane & 3;
    const int wm = wid >> 1, wn = wid & 1;

    float acc[2][4][4];
#pragma unroll
    for (int mt = 0; mt < 2; mt++)
#pragma unroll
        for (int nt = 0; nt < 4; nt++)
#pragma unroll
            for (int r = 0; r < 4; r++) acc[mt][nt][r] = 0.f;

    const int arow = tid >> 2, ac16 = tid & 3;          // A chunks: 2 iters
    const int brow = tid >> 2, bc16 = tid & 3;          // B chunks: 1 iter

    auto load_tiles = [&](int buf, int k0) {
        const uint32_t aOff = (uint32_t)(arow * RPAD + ac16 * 8) * 2;
        const uint32_t bOff = (uint32_t)(brow * RPAD + bc16 * 8) * 2;
        const uint32_t ah = sb + (buf ? OF_AH1 : OF_AH0) * 2;
        const uint32_t al = sb + (buf ? OF_AL1 : OF_AL0) * 2;
        const uint32_t bh = sb + (buf ? OF_BH1 : OF_BH0) * 2;
        const uint32_t bl = sb + (buf ? OF_BL1 : OF_BL0) * 2;
#pragma unroll
        for (int i = 0; i < 2; i++) {
            int row = arow + i * 64;
            uint32_t d = aOff + (uint32_t)(i * 64 * RPAD) * 2;
            const __nv_bfloat16* gs = Ah + (size_t)(m0 + row) * 1024 + k0 + ac16 * 8;
            const __nv_bfloat16* gl = Al + (size_t)(m0 + row) * 1024 + k0 + ac16 * 8;
            cp_async16(ah + d, gs);
            cp_async16(al + d, gl);
        }
        cp_async16(bh + bOff, Bh + (size_t)(n0 + brow) * 1024 + k0 + bc16 * 8);
        cp_async16(bl + bOff, Bl + (size_t)(n0 + brow) * 1024 + k0 + bc16 * 8);
        asm volatile("cp.async.commit_group;");
    };

    load_tiles(0, 0);

    for (int it = 0; it < 32; ++it) {
        const int cur = it & 1;
        if (it + 1 < 32) {
            load_tiles(cur ^ 1, (it + 1) * 32);
            asm volatile("cp.async.wait_group 1;");
        } else {
            asm volatile("cp.async.wait_group 0;");
        }
        __syncthreads();

        const uint32_t wAH = (cur ? OF_AH1 : OF_AH0) / 2;  // word offsets
        const uint32_t wAL = (cur ? OF_AL1 : OF_AL0) / 2;
        const uint32_t wBH = (cur ? OF_BH1 : OF_BH0) / 2;
        const uint32_t wBL = (cur ? OF_BL1 : OF_BL0) / 2;
#pragma unroll
        for (int kk = 0; kk < 2; kk++) {
            const int kw = kk * 8;  // word offset of k-half within row
            uint32_t ah[2][4], al[2][4];
#pragma unroll
            for (int mt = 0; mt < 2; mt++) {
                const int r0 = wm * 32 + mt * 16 + g;
                const uint32_t w0 = (uint32_t)r0 * 20 + kw + tg;
                const uint32_t w1 = (uint32_t)(r0 + 8) * 20 + kw + tg;
                ah[mt][0] = smw[wAH + w0];
                ah[mt][1] = smw[wAH + w1];
                ah[mt][2] = smw[wAH + w0 + 4];
                ah[mt][3] = smw[wAH + w1 + 4];
                al[mt][0] = smw[wAL + w0];
                al[mt][1] = smw[wAL + w1];
                al[mt][2] = smw[wAL + w0 + 4];
                al[mt][3] = smw[wAL + w1 + 4];
            }
#pragma unroll
            for (int nt = 0; nt < 4; nt++) {
                const int c0 = wn * 32 + nt * 8 + g;
                const uint32_t w0 = (uint32_t)c0 * 20 + kw + tg;
                uint32_t bh0 = smw[wBH + w0], bh1 = smw[wBH + w0 + 4];
                uint32_t bl0 = smw[wBL + w0], bl1 = smw[wBL + w0 + 4];
#pragma unroll
                for (int mt = 0; mt < 2; mt++) {
                    mma_bf16(acc[mt][nt], ah[mt][0], ah[mt][1], ah[mt][2], ah[mt][3],
                             bh0, bh1);
                    mma_bf16(acc[mt][nt], ah[mt][0], ah[mt][1], ah[mt][2], ah[mt][3],
                             bl0, bl1);
                    mma_bf16(acc[mt][nt], al[mt][0], al[mt][1], al[mt][2], al[mt][3],
                             bh0, bh1);
                }
            }
        }
        __syncthreads();
    }

#pragma unroll
    for (int mt = 0; mt < 2; mt++) {
        const int r0 = m0 + wm * 32 + mt * 16 + g;
#pragma unroll
        for (int nt = 0; nt < 4; nt++) {
            const int col = n0 + wn * 32 + nt * 8 + tg * 2;
            float bx = 0.f, by = 0.f;
            if (bias) {
                bx = bias[col];
                by = bias[col + 1];
            }
            float2 v0 = make_float2(acc[mt][nt][0] + bx, acc[mt][nt][1] + by);
            float2 v1 = make_float2(acc[mt][nt][2] + bx, acc[mt][nt][3] + by);
            *(float2*)(C + (size_t)r0 * 1024 + col) = v0;
            *(float2*)(C + (size_t)(r0 + 8) * 1024 + col) = v1;
        }
    }
}

// QKV fused: blockIdx.z selects W / output (z=0 adds e0 bias into Q).
__global__ __launch_bounds__(256) void gemm_qkv(const float* __restrict__ spk_emb) {
    const int z = blockIdx.z;
    const __nv_bfloat16* Bh = g_Wh + (size_t)z * NELEM;
    const __nv_bfloat16* Bl = g_Wl + (size_t)z * NELEM;
    float* C = (z == 0) ? g_Cq : (z == 1) ? g_Ck : g_Cv;
    const float* bias = (z == 0) ? spk_emb : nullptr;
    gemm_core(g_Ah, g_Al, Bh, Bl, C, bias, blockIdx.y * 128, blockIdx.x * 64);
}

__global__ __launch_bounds__(256) void gemm_out(float* __restrict__ out) {
    gemm_core(g_AOh, g_AOl, g_Wh + (size_t)3 * NELEM, g_Wl + (size_t)3 * NELEM,
              out, nullptr, blockIdx.y * 128, blockIdx.x * 64);
}

// ---------------------------------------------------------------------------
// Ghat[k][hs] = sum_{c<64} Wr[hs*64+c][k] * e0[hs*64+c]
// ---------------------------------------------------------------------------
__global__ __launch_bounds__(256) void ghat_kernel(const float* __restrict__ Wr,
                                                   const float* __restrict__ spk_emb) {
    __shared__ float part[128];
    const int kc = blockIdx.x;
    const int hs = blockIdx.y;
    const int kk = threadIdx.x & 127;
    const int ch = threadIdx.x >> 7;
    const float* base = Wr + (size_t)(hs * 64 + ch * 32) * 1024 + kc * 128 + kk;
    float s = 0.f;
#pragma unroll
    for (int c2 = 0; c2 < 32; c2++)
        s = fmaf(base[(size_t)c2 * 1024], spk_emb[hs * 64 + ch * 32 + c2], s);
    if (ch) part[kk] = s;
    __syncthreads();
    if (!ch) g_Ghat[(kc * 128 + kk) * 16 + hs] = s + part[kk];
}

// d[rr][hs] = rel_pe_2d[rr,:] @ Ghat[:,hs]
__global__ __launch_bounds__(128) void dmat_kernel(const float* __restrict__ relpe) {
    __shared__ float gh[2048];
    const int rrl = threadIdx.x >> 4, hs = threadIdx.x & 15;
    const int rr = blockIdx.x * 8 + rrl;
    float acc = 0.f;
    for (int chk = 0; chk < 8; chk++) {
        for (int i = threadIdx.x; i < 2048; i += 128) gh[i] = g_Ghat[chk * 2048 + i];
        __syncthreads();
        const float4* arow = (const float4*)(relpe + (size_t)rr * 1024 + chk * 128);
#pragma unroll
        for (int k4 = 0; k4 < 32; k4++) {
            float4 a = arow[k4];
            acc = fmaf(a.x, gh[(k4 * 4 + 0) * 16 + hs], acc);
            acc = fmaf(a.y, gh[(k4 * 4 + 1) * 16 + hs], acc);
            acc = fmaf(a.z, gh[(k4 * 4 + 2) * 16 + hs], acc);
            acc = fmaf(a.w, gh[(k4 * 4 + 3) * 16 + hs], acc);
        }
        __syncthreads();
    }
    g_dbuf[rr * 16 + hs] = acc;
}

// ---------------------------------------------------------------------------
// Fused attention per (b, h). Output written as bf16 hi/lo (feeds gemm_out).
// ---------------------------------------------------------------------------
#define QS_OFF 0
#define KS_OFF 8320
#define VS_OFF 16640
#define S_OFF 24960
#define E0_OFF 41472
#define E1_OFF 41536
#define CV_OFF 41600
#define SD0_OFF 41728
#define SD1_OFF 41856
#define ATTN_SMEM_FLOATS 41984
#define ATTN_SMEM_BYTES (ATTN_SMEM_FLOATS * 4)

__global__ __launch_bounds__(256) void attn_kernel(const int* __restrict__ spk_mask,
                                                   const float* __restrict__ spk_emb) {
    extern __shared__ float sm[];
    float* Qs = sm + QS_OFF;
    float* Ks = sm + KS_OFF;
    float* Vs = sm + VS_OFF;
    float* S = sm + S_OFF;
    float* e0h = sm + E0_OFF;
    float* e1h = sm + E1_OFF;
    float* cvec = sm + CV_OFF;
    float* sd0 = sm + SD0_OFF;
    float* sd1 = sm + SD1_OFF;

    const int b = blockIdx.x, h = blockIdx.y;
    const int tid = threadIdx.x;

    for (int idx = tid; idx < 128 * 64; idx += 256) {
        int i = idx >> 6, hd = idx & 63;
        size_t g = (size_t)(i * 8 + b) * 1024 + h * 64 + hd;
        Qs[i * 65 + hd] = g_Cq[g];
        Ks[i * 65 + hd] = g_Ck[g];
        Vs[i * 65 + hd] = g_Cv[g];
    }
    if (tid < 64) {
        e0h[tid] = spk_emb[h * 64 + tid];
        e1h[tid] = spk_emb[1024 + h * 64 + tid];
    } else if (tid < 192) {
        int j = tid - 64;
        cvec[j] = g_dbuf[(j * 8 + b) * 16 + h];
    }
    __syncthreads();

    if (tid < 128) {
        float s0 = 0.f, s1 = 0.f;
        const float* qrow = Qs + tid * 65;
#pragma unroll
        for (int k = 0; k < 64; k++) {
            float q = qrow[k];
            s0 = fmaf(q, e0h[k], s0);
            s1 = fmaf(q, e1h[k], s1);
        }
        sd0[tid] = s0;
        sd1[tid] = s1;
    }
    __syncthreads();

    const int ti = tid >> 4, tj = tid & 15;
    float acc[8][8];
#pragma unroll
    for (int a = 0; a < 8; a++)
#pragma unroll
        for (int c2 = 0; c2 < 8; c2++) acc[a][c2] = 0.f;
    for (int k = 0; k < 64; k++) {
        float qa[8], kb[8];
#pragma unroll
        for (int ii = 0; ii < 8; ii++) qa[ii] = Qs[(ti + 16 * ii) * 65 + k];
#pragma unroll
        for (int jj = 0; jj < 8; jj++) kb[jj] = Ks[(tj + 16 * jj) * 65 + k];
#pragma unroll
        for (int ii = 0; ii < 8; ii++)
#pragma unroll
            for (int jj = 0; jj < 8; jj++)
                acc[ii][jj] = fmaf(qa[ii], kb[jj], acc[ii][jj]);
    }
    const int* spm = spk_mask + b * 128 * 128;
#pragma unroll
    for (int ii = 0; ii < 8; ii++) {
        int i = ti + 16 * ii;
#pragma unroll
        for (int jj = 0; jj < 8; jj++) {
            int j = tj + 16 * jj;
            float v;
            if (j <= i) {
                float a2 = spm[i * 128 + j] ? sd1[i] : sd0[i];
                float a3 = cvec[127 - i + j];
                v = (acc[ii][jj] + a2 + a3) * 0.125f;
            } else {
                v = 1e-30f;
            }
            S[i * 129 + j] = v;
        }
    }
    __syncthreads();

    if (tid < 128) {
        float* row = S + tid * 129;
        float mx = row[0];
        for (int j = 1; j < 128; j++) mx = fmaxf(mx, row[j]);
        float sum = 0.f;
        for (int j = 0; j < 128; j++) {
            float e = __expf(row[j] - mx);
            row[j] = e;
            sum += e;
        }
        float inv = 1.f / sum;
        for (int j = 0; j < 128; j++) row[j] *= inv;
    }
    __syncthreads();

    const int r = tid >> 3, c = tid & 7;
    float oacc[4][8];
#pragma unroll
    for (int a = 0; a < 4; a++)
#pragma unroll
        for (int c2 = 0; c2 < 8; c2++) oacc[a][c2] = 0.f;
    for (int j = 0; j < 128; j++) {
        float wv[4], vv[8];
#pragma unroll
        for (int ii = 0; ii < 4; ii++) wv[ii] = S[(r + 32 * ii) * 129 + j];
#pragma unroll
        for (int jj = 0; jj < 8; jj++) vv[jj] = Vs[j * 65 + c + 8 * jj];
#pragma unroll
        for (int ii = 0; ii < 4; ii++)
#pragma unroll
            for (int jj = 0; jj < 8; jj++)
                oacc[ii][jj] = fmaf(wv[ii], vv[jj], oacc[ii][jj]);
    }
#pragma unroll
    for (int ii = 0; ii < 4; ii++) {
        int i = r + 32 * ii;
#pragma unroll
        for (int jj = 0; jj < 8; jj++) {
            int hd = c + 8 * jj;
            size_t g = (size_t)(i * 8 + b) * 1024 + h * 64 + hd;
            float v = oacc[ii][jj];
            __nv_bfloat16 hb = __float2bfloat16(v);
            float res = v - __bfloat162float(hb);
            g_AOh[g] = hb;
            g_AOl[g] = __float2bfloat16(res);
        }
    }
}

// ---------------------------------------------------------------------------
extern "C" void kernel_launch(void* const* d_in, const int* in_sizes, int n_in,
                              void* d_out, int out_size) {
    const float* query = (const float*)d_in[0];
    const float* rel_pe = (const float*)d_in[1];
    const float* Wq = (const float*)d_in[3];
    const float* Wk = (const float*)d_in[4];
    const float* Wv = (const float*)d_in[5];
    const float* Wr = (const float*)d_in[6];
    const float* Wo = (const float*)d_in[7];
    const float* spk_emb = (const float*)d_in[8];
    const int* spk_mask = (const int*)d_in[10];
    float* out = (float*)d_out;

    cudaFuncSetAttribute(attn_kernel, cudaFuncAttributeMaxDynamicSharedMemorySize,
                         ATTN_SMEM_BYTES);
    cudaFuncSetAttribute(gemm_qkv, cudaFuncAttributeMaxDynamicSharedMemorySize,
                         GEMM_SMEM_BYTES);
    cudaFuncSetAttribute(gemm_out, cudaFuncAttributeMaxDynamicSharedMemorySize,
                         GEMM_SMEM_BYTES);

    split5<<<dim3(1024, 5), 256>>>(query, Wq, Wk, Wv, Wo);
    gemm_qkv<<<dim3(16, 8, 3), 256, GEMM_SMEM_BYTES>>>(spk_emb);
    ghat_kernel<<<dim3(8, 16), 256>>>(Wr, spk_emb);
    dmat_kernel<<<128, 128>>>(rel_pe);
    attn_kernel<<<dim3(8, 16), 256, ATTN_SMEM_BYTES>>>(spk_mask, spk_emb);
    gemm_out<<<dim3(16, 8), 256, GEMM_SMEM_BYTES>>>(out);
}

// round 7
// speedup vs baseline: 3.1154x; 1.1512x over previous
#include <cuda_runtime.h>
#include <cuda_bf16.h>
#include <cstdint>

#define Dm 1024
#define NELEM (Dm * Dm)

// fp32 scratch
__device__ float g_Cq[NELEM];
__device__ float g_Ck[NELEM];
__device__ float g_Cv[NELEM];
__device__ float g_Ghat[Dm * 16];
__device__ float g_dpart[4][Dm * 16];   // k-chunk partials of d[rr][hs]
// bf16 hi/lo split scratch
__device__ __nv_bfloat16 g_Ah[NELEM], g_Al[NELEM];          // query
__device__ __nv_bfloat16 g_Wh[4 * NELEM], g_Wl[4 * NELEM];  // Wq,Wk,Wv,Wo
__device__ __nv_bfloat16 g_AOh[NELEM], g_AOl[NELEM];        // attention out

__device__ __forceinline__ void cp_async16(uint32_t s, const void* g) {
    asm volatile("cp.async.cg.shared.global [%0], [%1], 16;" :: "r"(s), "l"(g));
}
__device__ __forceinline__ uint32_t smem_u32(const void* p) {
    uint32_t a;
    asm("{ .reg .u64 t; cvta.to.shared.u64 t, %1; cvt.u32.u64 %0, t; }" : "=r"(a) : "l"(p));
    return a;
}
__device__ __forceinline__ void mma_bf16(float* c, uint32_t a0, uint32_t a1,
                                         uint32_t a2, uint32_t a3,
                                         uint32_t b0, uint32_t b1) {
    asm volatile(
        "mma.sync.aligned.m16n8k16.row.col.f32.bf16.bf16.f32 "
        "{%0,%1,%2,%3}, {%4,%5,%6,%7}, {%8,%9}, {%0,%1,%2,%3};"
        : "+f"(c[0]), "+f"(c[1]), "+f"(c[2]), "+f"(c[3])
        : "r"(a0), "r"(a1), "r"(a2), "r"(a3), "r"(b0), "r"(b1));
}

// ---------------------------------------------------------------------------
// split5: fp32 -> bf16 hi/lo for query + Wq/Wk/Wv/Wo. grid (1024, 5) x 256.
// ---------------------------------------------------------------------------
__global__ __launch_bounds__(256) void split5(const float* __restrict__ q,
                                              const float* __restrict__ wq,
                                              const float* __restrict__ wk,
                                              const float* __restrict__ wv,
                                              const float* __restrict__ wo) {
    const int arr = blockIdx.y;
    const float* src = (arr == 0) ? q : (arr == 1) ? wq : (arr == 2) ? wk
                                     : (arr == 3) ? wv : wo;
    __nv_bfloat16* hi = (arr == 0) ? g_Ah : g_Wh + (size_t)(arr - 1) * NELEM;
    __nv_bfloat16* lo = (arr == 0) ? g_Al : g_Wl + (size_t)(arr - 1) * NELEM;
    const int idx = (blockIdx.x * 256 + threadIdx.x) * 4;
    float4 v = *(const float4*)(src + idx);
    ushort4 h, l;
    float f[4] = {v.x, v.y, v.z, v.w};
    unsigned short hb[4], lb[4];
#pragma unroll
    for (int i = 0; i < 4; i++) {
        __nv_bfloat16 hv = __float2bfloat16(f[i]);
        float res = f[i] - __bfloat162float(hv);
        __nv_bfloat16 lv = __float2bfloat16(res);
        hb[i] = *(unsigned short*)&hv;
        lb[i] = *(unsigned short*)&lv;
    }
    h = make_ushort4(hb[0], hb[1], hb[2], hb[3]);
    l = make_ushort4(lb[0], lb[1], lb[2], lb[3]);
    *(ushort4*)(hi + idx) = h;
    *(ushort4*)(lo + idx) = l;
}

// ---------------------------------------------------------------------------
// bf16x3 GEMM core: C[1024][1024] = A @ W^T (+ bias), ~fp32 accuracy.
// ---------------------------------------------------------------------------
#define RPAD 40
#define A_T (128 * RPAD)
#define B_T (64 * RPAD)
#define OF_AH0 0
#define OF_AH1 A_T
#define OF_AL0 (2 * A_T)
#define OF_AL1 (3 * A_T)
#define OF_BH0 (4 * A_T)
#define OF_BH1 (4 * A_T + B_T)
#define OF_BL0 (4 * A_T + 2 * B_T)
#define OF_BL1 (4 * A_T + 3 * B_T)
#define GEMM_SMEM_BYTES ((4 * A_T + 4 * B_T) * 2)

__device__ __forceinline__ void gemm_core(const __nv_bfloat16* __restrict__ Ah,
                                          const __nv_bfloat16* __restrict__ Al,
                                          const __nv_bfloat16* __restrict__ Bh,
                                          const __nv_bfloat16* __restrict__ Bl,
                                          float* __restrict__ C,
                                          const float* __restrict__ bias,
                                          int m0, int n0) {
    extern __shared__ __nv_bfloat16 smb[];
    const uint32_t sb = smem_u32(smb);
    const uint32_t* smw = (const uint32_t*)smb;
    const int tid = threadIdx.x;
    const int wid = tid >> 5, lane = tid & 31;
    const int g = lane >> 2, tg = lane & 3;
    const int wm = wid >> 1, wn = wid & 1;

    float acc[2][4][4];
#pragma unroll
    for (int mt = 0; mt < 2; mt++)
#pragma unroll
        for (int nt = 0; nt < 4; nt++)
#pragma unroll
            for (int r = 0; r < 4; r++) acc[mt][nt][r] = 0.f;

    const int arow = tid >> 2, ac16 = tid & 3;

    auto load_tiles = [&](int buf, int k0) {
        const uint32_t aOff = (uint32_t)(arow * RPAD + ac16 * 8) * 2;
        const uint32_t ah = sb + (buf ? OF_AH1 : OF_AH0) * 2;
        const uint32_t al = sb + (buf ? OF_AL1 : OF_AL0) * 2;
        const uint32_t bh = sb + (buf ? OF_BH1 : OF_BH0) * 2;
        const uint32_t bl = sb + (buf ? OF_BL1 : OF_BL0) * 2;
#pragma unroll
        for (int i = 0; i < 2; i++) {
            int row = arow + i * 64;
            uint32_t d = aOff + (uint32_t)(i * 64 * RPAD) * 2;
            cp_async16(ah + d, Ah + (size_t)(m0 + row) * 1024 + k0 + ac16 * 8);
            cp_async16(al + d, Al + (size_t)(m0 + row) * 1024 + k0 + ac16 * 8);
        }
        cp_async16(bh + aOff, Bh + (size_t)(n0 + arow) * 1024 + k0 + ac16 * 8);
        cp_async16(bl + aOff, Bl + (size_t)(n0 + arow) * 1024 + k0 + ac16 * 8);
        asm volatile("cp.async.commit_group;");
    };

    load_tiles(0, 0);

    for (int it = 0; it < 32; ++it) {
        const int cur = it & 1;
        if (it + 1 < 32) {
            load_tiles(cur ^ 1, (it + 1) * 32);
            asm volatile("cp.async.wait_group 1;");
        } else {
            asm volatile("cp.async.wait_group 0;");
        }
        __syncthreads();

        const uint32_t wAH = (cur ? OF_AH1 : OF_AH0) / 2;
        const uint32_t wAL = (cur ? OF_AL1 : OF_AL0) / 2;
        const uint32_t wBH = (cur ? OF_BH1 : OF_BH0) / 2;
        const uint32_t wBL = (cur ? OF_BL1 : OF_BL0) / 2;
#pragma unroll
        for (int kk = 0; kk < 2; kk++) {
            const int kw = kk * 8;
            uint32_t ah[2][4], al[2][4];
#pragma unroll
            for (int mt = 0; mt < 2; mt++) {
                const int r0 = wm * 32 + mt * 16 + g;
                const uint32_t w0 = (uint32_t)r0 * 20 + kw + tg;
                const uint32_t w1 = (uint32_t)(r0 + 8) * 20 + kw + tg;
                ah[mt][0] = smw[wAH + w0];
                ah[mt][1] = smw[wAH + w1];
                ah[mt][2] = smw[wAH + w0 + 4];
                ah[mt][3] = smw[wAH + w1 + 4];
                al[mt][0] = smw[wAL + w0];
                al[mt][1] = smw[wAL + w1];
                al[mt][2] = smw[wAL + w0 + 4];
                al[mt][3] = smw[wAL + w1 + 4];
            }
#pragma unroll
            for (int nt = 0; nt < 4; nt++) {
                const int c0 = wn * 32 + nt * 8 + g;
                const uint32_t w0 = (uint32_t)c0 * 20 + kw + tg;
                uint32_t bh0 = smw[wBH + w0], bh1 = smw[wBH + w0 + 4];
                uint32_t bl0 = smw[wBL + w0], bl1 = smw[wBL + w0 + 4];
#pragma unroll
                for (int mt = 0; mt < 2; mt++) {
                    mma_bf16(acc[mt][nt], ah[mt][0], ah[mt][1], ah[mt][2], ah[mt][3],
                             bh0, bh1);
                    mma_bf16(acc[mt][nt], ah[mt][0], ah[mt][1], ah[mt][2], ah[mt][3],
                             bl0, bl1);
                    mma_bf16(acc[mt][nt], al[mt][0], al[mt][1], al[mt][2], al[mt][3],
                             bh0, bh1);
                }
            }
        }
        __syncthreads();
    }

#pragma unroll
    for (int mt = 0; mt < 2; mt++) {
        const int r0 = m0 + wm * 32 + mt * 16 + g;
#pragma unroll
        for (int nt = 0; nt < 4; nt++) {
            const int col = n0 + wn * 32 + nt * 8 + tg * 2;
            float bx = 0.f, by = 0.f;
            if (bias) {
                bx = bias[col];
                by = bias[col + 1];
            }
            float2 v0 = make_float2(acc[mt][nt][0] + bx, acc[mt][nt][1] + by);
            float2 v1 = make_float2(acc[mt][nt][2] + bx, acc[mt][nt][3] + by);
            *(float2*)(C + (size_t)r0 * 1024 + col) = v0;
            *(float2*)(C + (size_t)(r0 + 8) * 1024 + col) = v1;
        }
    }
}

__global__ __launch_bounds__(256) void gemm_qkv(const float* __restrict__ spk_emb) {
    const int z = blockIdx.z;
    const __nv_bfloat16* Bh = g_Wh + (size_t)z * NELEM;
    const __nv_bfloat16* Bl = g_Wl + (size_t)z * NELEM;
    float* C = (z == 0) ? g_Cq : (z == 1) ? g_Ck : g_Cv;
    const float* bias = (z == 0) ? spk_emb : nullptr;
    gemm_core(g_Ah, g_Al, Bh, Bl, C, bias, blockIdx.y * 128, blockIdx.x * 64);
}

__global__ __launch_bounds__(256) void gemm_out(float* __restrict__ out) {
    gemm_core(g_AOh, g_AOl, g_Wh + (size_t)3 * NELEM, g_Wl + (size_t)3 * NELEM,
              out, nullptr, blockIdx.y * 128, blockIdx.x * 64);
}

// ---------------------------------------------------------------------------
// Ghat[k][hs] = sum_{c<64} Wr[hs*64+c][k] * e0[hs*64+c]
// ---------------------------------------------------------------------------
__global__ __launch_bounds__(256) void ghat_kernel(const float* __restrict__ Wr,
                                                   const float* __restrict__ spk_emb) {
    __shared__ float part[128];
    const int kc = blockIdx.x;
    const int hs = blockIdx.y;
    const int kk = threadIdx.x & 127;
    const int ch = threadIdx.x >> 7;
    const float* base = Wr + (size_t)(hs * 64 + ch * 32) * 1024 + kc * 128 + kk;
    float s = 0.f;
#pragma unroll
    for (int c2 = 0; c2 < 32; c2++)
        s = fmaf(base[(size_t)c2 * 1024], spk_emb[hs * 64 + ch * 32 + c2], s);
    if (ch) part[kk] = s;
    __syncthreads();
    if (!ch) g_Ghat[(kc * 128 + kk) * 16 + hs] = s + part[kk];
}

// ---------------------------------------------------------------------------
// dmat partials: g_dpart[chunk][rr][hs] = sum_{k in chunk} relpe2d[rr,k]*Ghat[k,hs]
// grid (64 rr-groups, 4 k-chunks) x 256 threads. No smem, no syncthreads:
// per-thread 4 independent accumulators, coalesced Ghat reads (L2-resident).
// ---------------------------------------------------------------------------
__global__ __launch_bounds__(256) void dmat_kernel(const float* __restrict__ relpe) {
    const int rr = blockIdx.x * 16 + (threadIdx.x >> 4);
    const int hs = threadIdx.x & 15;
    const int k0 = blockIdx.y * 256;
    const float4* arow = (const float4*)(relpe + (size_t)rr * 1024 + k0);
    const float* gh = g_Ghat + (size_t)k0 * 16 + hs;
    float a0 = 0.f, a1 = 0.f, a2 = 0.f, a3 = 0.f;
#pragma unroll
    for (int k4 = 0; k4 < 64; k4++) {
        float4 a = arow[k4];
        a0 = fmaf(a.x, gh[(k4 * 4 + 0) * 16], a0);
        a1 = fmaf(a.y, gh[(k4 * 4 + 1) * 16], a1);
        a2 = fmaf(a.z, gh[(k4 * 4 + 2) * 16], a2);
        a3 = fmaf(a.w, gh[(k4 * 4 + 3) * 16], a3);
    }
    g_dpart[blockIdx.y][rr * 16 + hs] = (a0 + a1) + (a2 + a3);
}

// ---------------------------------------------------------------------------
// Fused attention per (b, h). Output written as bf16 hi/lo (feeds gemm_out).
// ---------------------------------------------------------------------------
#define QS_OFF 0
#define KS_OFF 8320
#define VS_OFF 16640
#define S_OFF 24960
#define E0_OFF 41472
#define E1_OFF 41536
#define CV_OFF 41600
#define SD0_OFF 41728
#define SD1_OFF 41856
#define ATTN_SMEM_FLOATS 41984
#define ATTN_SMEM_BYTES (ATTN_SMEM_FLOATS * 4)

__global__ __launch_bounds__(256) void attn_kernel(const int* __restrict__ spk_mask,
                                                   const float* __restrict__ spk_emb) {
    extern __shared__ float sm[];
    float* Qs = sm + QS_OFF;
    float* Ks = sm + KS_OFF;
    float* Vs = sm + VS_OFF;
    float* S = sm + S_OFF;
    float* e0h = sm + E0_OFF;
    float* e1h = sm + E1_OFF;
    float* cvec = sm + CV_OFF;
    float* sd0 = sm + SD0_OFF;
    float* sd1 = sm + SD1_OFF;

    const int b = blockIdx.x, h = blockIdx.y;
    const int tid = threadIdx.x;

    for (int idx = tid; idx < 128 * 64; idx += 256) {
        int i = idx >> 6, hd = idx & 63;
        size_t g = (size_t)(i * 8 + b) * 1024 + h * 64 + hd;
        Qs[i * 65 + hd] = g_Cq[g];
        Ks[i * 65 + hd] = g_Ck[g];
        Vs[i * 65 + hd] = g_Cv[g];
    }
    if (tid < 64) {
        e0h[tid] = spk_emb[h * 64 + tid];
        e1h[tid] = spk_emb[1024 + h * 64 + tid];
    } else if (tid < 192) {
        int j = tid - 64;
        int off = (j * 8 + b) * 16 + h;
        cvec[j] = (g_dpart[0][off] + g_dpart[1][off]) +
                  (g_dpart[2][off] + g_dpart[3][off]);
    }
    __syncthreads();

    if (tid < 128) {
        float s0 = 0.f, s1 = 0.f;
        const float* qrow = Qs + tid * 65;
#pragma unroll
        for (int k = 0; k < 64; k++) {
            float q = qrow[k];
            s0 = fmaf(q, e0h[k], s0);
            s1 = fmaf(q, e1h[k], s1);
        }
        sd0[tid] = s0;
        sd1[tid] = s1;
    }
    __syncthreads();

    const int ti = tid >> 4, tj = tid & 15;
    float acc[8][8];
#pragma unroll
    for (int a = 0; a < 8; a++)
#pragma unroll
        for (int c2 = 0; c2 < 8; c2++) acc[a][c2] = 0.f;
    for (int k = 0; k < 64; k++) {
        float qa[8], kb[8];
#pragma unroll
        for (int ii = 0; ii < 8; ii++) qa[ii] = Qs[(ti + 16 * ii) * 65 + k];
#pragma unroll
        for (int jj = 0; jj < 8; jj++) kb[jj] = Ks[(tj + 16 * jj) * 65 + k];
#pragma unroll
        for (int ii = 0; ii < 8; ii++)
#pragma unroll
            for (int jj = 0; jj < 8; jj++)
                acc[ii][jj] = fmaf(qa[ii], kb[jj], acc[ii][jj]);
    }
    const int* spm = spk_mask + b * 128 * 128;
#pragma unroll
    for (int ii = 0; ii < 8; ii++) {
        int i = ti + 16 * ii;
#pragma unroll
        for (int jj = 0; jj < 8; jj++) {
            int j = tj + 16 * jj;
            float v;
            if (j <= i) {
                float a2 = spm[i * 128 + j] ? sd1[i] : sd0[i];
                float a3 = cvec[127 - i + j];
                v = (acc[ii][jj] + a2 + a3) * 0.125f;
            } else {
                v = 1e-30f;
            }
            S[i * 129 + j] = v;
        }
    }
    __syncthreads();

    if (tid < 128) {
        float* row = S + tid * 129;
        float mx = row[0];
        for (int j = 1; j < 128; j++) mx = fmaxf(mx, row[j]);
        float sum = 0.f;
        for (int j = 0; j < 128; j++) {
            float e = __expf(row[j] - mx);
            row[j] = e;
            sum += e;
        }
        float inv = 1.f / sum;
        for (int j = 0; j < 128; j++) row[j] *= inv;
    }
    __syncthreads();

    const int r = tid >> 3, c = tid & 7;
    float oacc[4][8];
#pragma unroll
    for (int a = 0; a < 4; a++)
#pragma unroll
        for (int c2 = 0; c2 < 8; c2++) oacc[a][c2] = 0.f;
    for (int j = 0; j < 128; j++) {
        float wv[4], vv[8];
#pragma unroll
        for (int ii = 0; ii < 4; ii++) wv[ii] = S[(r + 32 * ii) * 129 + j];
#pragma unroll
        for (int jj = 0; jj < 8; jj++) vv[jj] = Vs[j * 65 + c + 8 * jj];
#pragma unroll
        for (int ii = 0; ii < 4; ii++)
#pragma unroll
            for (int jj = 0; jj < 8; jj++)
                oacc[ii][jj] = fmaf(wv[ii], vv[jj], oacc[ii][jj]);
    }
#pragma unroll
    for (int ii = 0; ii < 4; ii++) {
        int i = r + 32 * ii;
#pragma unroll
        for (int jj = 0; jj < 8; jj++) {
            int hd = c + 8 * jj;
            size_t g = (size_t)(i * 8 + b) * 1024 + h * 64 + hd;
            float v = oacc[ii][jj];
            __nv_bfloat16 hb = __float2bfloat16(v);
            float res = v - __bfloat162float(hb);
            g_AOh[g] = hb;
            g_AOl[g] = __float2bfloat16(res);
        }
    }
}

// ---------------------------------------------------------------------------
extern "C" void kernel_launch(void* const* d_in, const int* in_sizes, int n_in,
                              void* d_out, int out_size) {
    const float* query = (const float*)d_in[0];
    const float* rel_pe = (const float*)d_in[1];
    const float* Wq = (const float*)d_in[3];
    const float* Wk = (const float*)d_in[4];
    const float* Wv = (const float*)d_in[5];
    const float* Wr = (const float*)d_in[6];
    const float* Wo = (const float*)d_in[7];
    const float* spk_emb = (const float*)d_in[8];
    const int* spk_mask = (const int*)d_in[10];
    float* out = (float*)d_out;

    cudaFuncSetAttribute(attn_kernel, cudaFuncAttributeMaxDynamicSharedMemorySize,
                         ATTN_SMEM_BYTES);
    cudaFuncSetAttribute(gemm_qkv, cudaFuncAttributeMaxDynamicSharedMemorySize,
                         GEMM_SMEM_BYTES);
    cudaFuncSetAttribute(gemm_out, cudaFuncAttributeMaxDynamicSharedMemorySize,
                         GEMM_SMEM_BYTES);

    split5<<<dim3(1024, 5), 256>>>(query, Wq, Wk, Wv, Wo);
    gemm_qkv<<<dim3(16, 8, 3), 256, GEMM_SMEM_BYTES>>>(spk_emb);
    ghat_kernel<<<dim3(8, 16), 256>>>(Wr, spk_emb);
    dmat_kernel<<<dim3(64, 4), 256>>>(rel_pe);
    attn_kernel<<<dim3(8, 16), 256, ATTN_SMEM_BYTES>>>(spk_mask, spk_emb);
    gemm_out<<<dim3(16, 8), 256, GEMM_SMEM_BYTES>>>(out);
}

// round 8
// speedup vs baseline: 3.2618x; 1.0470x over previous
#include <cuda_runtime.h>
#include <cuda_bf16.h>
#include <cstdint>

#define Dm 1024
#define NELEM (Dm * Dm)

// fp32 scratch
__device__ float g_Cq[NELEM];
__device__ float g_Ck[NELEM];
__device__ float g_Cv[NELEM];
__device__ float g_GhatT[16 * Dm];      // [hs][k]
__device__ float g_dpart[4][Dm * 16];   // k-chunk partials of d[rr][hs]
// bf16 hi/lo split scratch
__device__ __nv_bfloat16 g_Ah[NELEM], g_Al[NELEM];          // query
__device__ __nv_bfloat16 g_Wh[4 * NELEM], g_Wl[4 * NELEM];  // Wq,Wk,Wv,Wo
__device__ __nv_bfloat16 g_AOh[NELEM], g_AOl[NELEM];        // attention out

__device__ __forceinline__ void cp_async16(uint32_t s, const void* g) {
    asm volatile("cp.async.cg.shared.global [%0], [%1], 16;" :: "r"(s), "l"(g));
}
__device__ __forceinline__ uint32_t smem_u32(const void* p) {
    uint32_t a;
    asm("{ .reg .u64 t; cvta.to.shared.u64 t, %1; cvt.u32.u64 %0, t; }" : "=r"(a) : "l"(p));
    return a;
}
__device__ __forceinline__ void mma_bf16(float* c, uint32_t a0, uint32_t a1,
                                         uint32_t a2, uint32_t a3,
                                         uint32_t b0, uint32_t b1) {
    asm volatile(
        "mma.sync.aligned.m16n8k16.row.col.f32.bf16.bf16.f32 "
        "{%0,%1,%2,%3}, {%4,%5,%6,%7}, {%8,%9}, {%0,%1,%2,%3};"
        : "+f"(c[0]), "+f"(c[1]), "+f"(c[2]), "+f"(c[3])
        : "r"(a0), "r"(a1), "r"(a2), "r"(a3), "r"(b0), "r"(b1));
}

// ---------------------------------------------------------------------------
// split5 + ghat fused. grid (1024, 6) x 256.
//   y in [0,5): fp32 -> bf16 hi/lo split of query + Wq/Wk/Wv/Wo
//   y == 5, x < 128: GhatT[hs][k] = sum_{c<64} Wr[hs*64+c][k] * e0[hs*64+c]
// ---------------------------------------------------------------------------
__global__ __launch_bounds__(256) void split_ghat(const float* __restrict__ q,
                                                  const float* __restrict__ wq,
                                                  const float* __restrict__ wk,
                                                  const float* __restrict__ wv,
                                                  const float* __restrict__ wo,
                                                  const float* __restrict__ Wr,
                                                  const float* __restrict__ spk_emb) {
    const int arr = blockIdx.y;
    if (arr == 5) {
        if (blockIdx.x >= 128) return;
        __shared__ float part[128];
        const int kc = blockIdx.x & 7;        // k-chunk
        const int hs = blockIdx.x >> 3;       // head
        const int kk = threadIdx.x & 127;
        const int ch = threadIdx.x >> 7;
        const float* base = Wr + (size_t)(hs * 64 + ch * 32) * 1024 + kc * 128 + kk;
        float s = 0.f;
#pragma unroll
        for (int c2 = 0; c2 < 32; c2++)
            s = fmaf(base[(size_t)c2 * 1024], spk_emb[hs * 64 + ch * 32 + c2], s);
        if (ch) part[kk] = s;
        __syncthreads();
        if (!ch) g_GhatT[hs * 1024 + kc * 128 + kk] = s + part[kk];
        return;
    }
    const float* src = (arr == 0) ? q : (arr == 1) ? wq : (arr == 2) ? wk
                                     : (arr == 3) ? wv : wo;
    __nv_bfloat16* hi = (arr == 0) ? g_Ah : g_Wh + (size_t)(arr - 1) * NELEM;
    __nv_bfloat16* lo = (arr == 0) ? g_Al : g_Wl + (size_t)(arr - 1) * NELEM;
    const int idx = (blockIdx.x * 256 + threadIdx.x) * 4;
    float4 v = *(const float4*)(src + idx);
    float f[4] = {v.x, v.y, v.z, v.w};
    unsigned short hb[4], lb[4];
#pragma unroll
    for (int i = 0; i < 4; i++) {
        __nv_bfloat16 hv = __float2bfloat16(f[i]);
        float res = f[i] - __bfloat162float(hv);
        __nv_bfloat16 lv = __float2bfloat16(res);
        hb[i] = *(unsigned short*)&hv;
        lb[i] = *(unsigned short*)&lv;
    }
    *(ushort4*)(hi + idx) = make_ushort4(hb[0], hb[1], hb[2], hb[3]);
    *(ushort4*)(lo + idx) = make_ushort4(lb[0], lb[1], lb[2], lb[3]);
}

// ---------------------------------------------------------------------------
// bf16x3 GEMM core: C[1024][1024] = A @ W^T (+ bias), ~fp32 accuracy.
// ---------------------------------------------------------------------------
#define RPAD 40
#define A_T (128 * RPAD)
#define B_T (64 * RPAD)
#define OF_AH0 0
#define OF_AH1 A_T
#define OF_AL0 (2 * A_T)
#define OF_AL1 (3 * A_T)
#define OF_BH0 (4 * A_T)
#define OF_BH1 (4 * A_T + B_T)
#define OF_BL0 (4 * A_T + 2 * B_T)
#define OF_BL1 (4 * A_T + 3 * B_T)
#define GEMM_SMEM_BYTES ((4 * A_T + 4 * B_T) * 2)

__device__ __forceinline__ void gemm_core(const __nv_bfloat16* __restrict__ Ah,
                                          const __nv_bfloat16* __restrict__ Al,
                                          const __nv_bfloat16* __restrict__ Bh,
                                          const __nv_bfloat16* __restrict__ Bl,
                                          float* __restrict__ C,
                                          const float* __restrict__ bias,
                                          int m0, int n0) {
    extern __shared__ __nv_bfloat16 smb[];
    const uint32_t sb = smem_u32(smb);
    const uint32_t* smw = (const uint32_t*)smb;
    const int tid = threadIdx.x;
    const int wid = tid >> 5, lane = tid & 31;
    const int g = lane >> 2, tg = lane & 3;
    const int wm = wid >> 1, wn = wid & 1;

    float acc[2][4][4];
#pragma unroll
    for (int mt = 0; mt < 2; mt++)
#pragma unroll
        for (int nt = 0; nt < 4; nt++)
#pragma unroll
            for (int r = 0; r < 4; r++) acc[mt][nt][r] = 0.f;

    const int arow = tid >> 2, ac16 = tid & 3;

    auto load_tiles = [&](int buf, int k0) {
        const uint32_t aOff = (uint32_t)(arow * RPAD + ac16 * 8) * 2;
        const uint32_t ah = sb + (buf ? OF_AH1 : OF_AH0) * 2;
        const uint32_t al = sb + (buf ? OF_AL1 : OF_AL0) * 2;
        const uint32_t bh = sb + (buf ? OF_BH1 : OF_BH0) * 2;
        const uint32_t bl = sb + (buf ? OF_BL1 : OF_BL0) * 2;
#pragma unroll
        for (int i = 0; i < 2; i++) {
            int row = arow + i * 64;
            uint32_t d = aOff + (uint32_t)(i * 64 * RPAD) * 2;
            cp_async16(ah + d, Ah + (size_t)(m0 + row) * 1024 + k0 + ac16 * 8);
            cp_async16(al + d, Al + (size_t)(m0 + row) * 1024 + k0 + ac16 * 8);
        }
        cp_async16(bh + aOff, Bh + (size_t)(n0 + arow) * 1024 + k0 + ac16 * 8);
        cp_async16(bl + aOff, Bl + (size_t)(n0 + arow) * 1024 + k0 + ac16 * 8);
        asm volatile("cp.async.commit_group;");
    };

    load_tiles(0, 0);

    for (int it = 0; it < 32; ++it) {
        const int cur = it & 1;
        if (it + 1 < 32) {
            load_tiles(cur ^ 1, (it + 1) * 32);
            asm volatile("cp.async.wait_group 1;");
        } else {
            asm volatile("cp.async.wait_group 0;");
        }
        __syncthreads();

        const uint32_t wAH = (cur ? OF_AH1 : OF_AH0) / 2;
        const uint32_t wAL = (cur ? OF_AL1 : OF_AL0) / 2;
        const uint32_t wBH = (cur ? OF_BH1 : OF_BH0) / 2;
        const uint32_t wBL = (cur ? OF_BL1 : OF_BL0) / 2;
#pragma unroll
        for (int kk = 0; kk < 2; kk++) {
            const int kw = kk * 8;
            uint32_t ah[2][4], al[2][4];
#pragma unroll
            for (int mt = 0; mt < 2; mt++) {
                const int r0 = wm * 32 + mt * 16 + g;
                const uint32_t w0 = (uint32_t)r0 * 20 + kw + tg;
                const uint32_t w1 = (uint32_t)(r0 + 8) * 20 + kw + tg;
                ah[mt][0] = smw[wAH + w0];
                ah[mt][1] = smw[wAH + w1];
                ah[mt][2] = smw[wAH + w0 + 4];
                ah[mt][3] = smw[wAH + w1 + 4];
                al[mt][0] = smw[wAL + w0];
                al[mt][1] = smw[wAL + w1];
                al[mt][2] = smw[wAL + w0 + 4];
                al[mt][3] = smw[wAL + w1 + 4];
            }
#pragma unroll
            for (int nt = 0; nt < 4; nt++) {
                const int c0 = wn * 32 + nt * 8 + g;
                const uint32_t w0 = (uint32_t)c0 * 20 + kw + tg;
                uint32_t bh0 = smw[wBH + w0], bh1 = smw[wBH + w0 + 4];
                uint32_t bl0 = smw[wBL + w0], bl1 = smw[wBL + w0 + 4];
#pragma unroll
                for (int mt = 0; mt < 2; mt++) {
                    mma_bf16(acc[mt][nt], ah[mt][0], ah[mt][1], ah[mt][2], ah[mt][3],
                             bh0, bh1);
                    mma_bf16(acc[mt][nt], ah[mt][0], ah[mt][1], ah[mt][2], ah[mt][3],
                             bl0, bl1);
                    mma_bf16(acc[mt][nt], al[mt][0], al[mt][1], al[mt][2], al[mt][3],
                             bh0, bh1);
                }
            }
        }
        __syncthreads();
    }

#pragma unroll
    for (int mt = 0; mt < 2; mt++) {
        const int r0 = m0 + wm * 32 + mt * 16 + g;
#pragma unroll
        for (int nt = 0; nt < 4; nt++) {
            const int col = n0 + wn * 32 + nt * 8 + tg * 2;
            float bx = 0.f, by = 0.f;
            if (bias) {
                bx = bias[col];
                by = bias[col + 1];
            }
            float2 v0 = make_float2(acc[mt][nt][0] + bx, acc[mt][nt][1] + by);
            float2 v1 = make_float2(acc[mt][nt][2] + bx, acc[mt][nt][3] + by);
            *(float2*)(C + (size_t)r0 * 1024 + col) = v0;
            *(float2*)(C + (size_t)(r0 + 8) * 1024 + col) = v1;
        }
    }
}

// ---------------------------------------------------------------------------
// Fused mid kernel: z in [0,3) -> QKV GEMMs; z in {3,4} -> dmat partials.
// dmat: g_dpart[chunk][rr][hs] = sum_{k in chunk of 256} relpe2d[rr,k]*GhatT[hs,k]
// ---------------------------------------------------------------------------
__global__ __launch_bounds__(256) void gemm_mid(const float* __restrict__ spk_emb,
                                                const float* __restrict__ relpe) {
    const int z = blockIdx.z;
    if (z < 3) {
        const __nv_bfloat16* Bh = g_Wh + (size_t)z * NELEM;
        const __nv_bfloat16* Bl = g_Wl + (size_t)z * NELEM;
        float* C = (z == 0) ? g_Cq : (z == 1) ? g_Ck : g_Cv;
        const float* bias = (z == 0) ? spk_emb : nullptr;
        gemm_core(g_Ah, g_Al, Bh, Bl, C, bias, blockIdx.y * 128, blockIdx.x * 64);
        return;
    }
    // dmat: f in [0,256)
    const int f = (z - 3) * 128 + blockIdx.y * 16 + blockIdx.x;
    const int chunk = f & 3;
    const int rr = (f >> 2) * 16 + (threadIdx.x >> 4);
    const int hs = threadIdx.x & 15;
    const int k0 = chunk * 256;
    const float4* arow = (const float4*)(relpe + (size_t)rr * 1024 + k0);
    const float4* grow = (const float4*)(g_GhatT + (size_t)hs * 1024 + k0);
    float a0 = 0.f, a1 = 0.f, a2 = 0.f, a3 = 0.f;
#pragma unroll 8
    for (int k4 = 0; k4 < 64; k4++) {
        float4 a = arow[k4];
        float4 gv = grow[k4];
        a0 = fmaf(a.x, gv.x, a0);
        a1 = fmaf(a.y, gv.y, a1);
        a2 = fmaf(a.z, gv.z, a2);
        a3 = fmaf(a.w, gv.w, a3);
    }
    g_dpart[chunk][rr * 16 + hs] = (a0 + a1) + (a2 + a3);
}

__global__ __launch_bounds__(256) void gemm_out(float* __restrict__ out) {
    gemm_core(g_AOh, g_AOl, g_Wh + (size_t)3 * NELEM, g_Wl + (size_t)3 * NELEM,
              out, nullptr, blockIdx.y * 128, blockIdx.x * 64);
}

// ---------------------------------------------------------------------------
// Fused attention per (b, h). Output written as bf16 hi/lo (feeds gemm_out).
// ---------------------------------------------------------------------------
#define QS_OFF 0
#define KS_OFF 8320
#define VS_OFF 16640
#define S_OFF 24960
#define E0_OFF 41472
#define E1_OFF 41536
#define CV_OFF 41600
#define SD0_OFF 41728
#define SD1_OFF 41856
#define ATTN_SMEM_FLOATS 41984
#define ATTN_SMEM_BYTES (ATTN_SMEM_FLOATS * 4)

__global__ __launch_bounds__(256) void attn_kernel(const int* __restrict__ spk_mask,
                                                   const float* __restrict__ spk_emb) {
    extern __shared__ float sm[];
    float* Qs = sm + QS_OFF;
    float* Ks = sm + KS_OFF;
    float* Vs = sm + VS_OFF;
    float* S = sm + S_OFF;
    float* e0h = sm + E0_OFF;
    float* e1h = sm + E1_OFF;
    float* cvec = sm + CV_OFF;
    float* sd0 = sm + SD0_OFF;
    float* sd1 = sm + SD1_OFF;

    const int b = blockIdx.x, h = blockIdx.y;
    const int tid = threadIdx.x;

    for (int idx = tid; idx < 128 * 64; idx += 256) {
        int i = idx >> 6, hd = idx & 63;
        size_t g = (size_t)(i * 8 + b) * 1024 + h * 64 + hd;
        Qs[i * 65 + hd] = g_Cq[g];
        Ks[i * 65 + hd] = g_Ck[g];
        Vs[i * 65 + hd] = g_Cv[g];
    }
    if (tid < 64) {
        e0h[tid] = spk_emb[h * 64 + tid];
        e1h[tid] = spk_emb[1024 + h * 64 + tid];
    } else if (tid < 192) {
        int j = tid - 64;
        int off = (j * 8 + b) * 16 + h;
        cvec[j] = (g_dpart[0][off] + g_dpart[1][off]) +
                  (g_dpart[2][off] + g_dpart[3][off]);
    }
    __syncthreads();

    if (tid < 128) {
        float s0 = 0.f, s1 = 0.f;
        const float* qrow = Qs + tid * 65;
#pragma unroll
        for (int k = 0; k < 64; k++) {
            float q = qrow[k];
            s0 = fmaf(q, e0h[k], s0);
            s1 = fmaf(q, e1h[k], s1);
        }
        sd0[tid] = s0;
        sd1[tid] = s1;
    }
    __syncthreads();

    const int ti = tid >> 4, tj = tid & 15;
    float acc[8][8];
#pragma unroll
    for (int a = 0; a < 8; a++)
#pragma unroll
        for (int c2 = 0; c2 < 8; c2++) acc[a][c2] = 0.f;
    for (int k = 0; k < 64; k++) {
        float qa[8], kb[8];
#pragma unroll
        for (int ii = 0; ii < 8; ii++) qa[ii] = Qs[(ti + 16 * ii) * 65 + k];
#pragma unroll
        for (int jj = 0; jj < 8; jj++) kb[jj] = Ks[(tj + 16 * jj) * 65 + k];
#pragma unroll
        for (int ii = 0; ii < 8; ii++)
#pragma unroll
            for (int jj = 0; jj < 8; jj++)
                acc[ii][jj] = fmaf(qa[ii], kb[jj], acc[ii][jj]);
    }
    const int* spm = spk_mask + b * 128 * 128;
#pragma unroll
    for (int ii = 0; ii < 8; ii++) {
        int i = ti + 16 * ii;
#pragma unroll
        for (int jj = 0; jj < 8; jj++) {
            int j = tj + 16 * jj;
            float v;
            if (j <= i) {
                float a2 = spm[i * 128 + j] ? sd1[i] : sd0[i];
                float a3 = cvec[127 - i + j];
                v = (acc[ii][jj] + a2 + a3) * 0.125f;
            } else {
                v = 1e-30f;
            }
            S[i * 129 + j] = v;
        }
    }
    __syncthreads();

    if (tid < 128) {
        float* row = S + tid * 129;
        float mx = row[0];
        for (int j = 1; j < 128; j++) mx = fmaxf(mx, row[j]);
        float sum = 0.f;
        for (int j = 0; j < 128; j++) {
            float e = __expf(row[j] - mx);
            row[j] = e;
            sum += e;
        }
        float inv = 1.f / sum;
        for (int j = 0; j < 128; j++) row[j] *= inv;
    }
    __syncthreads();

    const int r = tid >> 3, c = tid & 7;
    float oacc[4][8];
#pragma unroll
    for (int a = 0; a < 4; a++)
#pragma unroll
        for (int c2 = 0; c2 < 8; c2++) oacc[a][c2] = 0.f;
    for (int j = 0; j < 128; j++) {
        float wv[4], vv[8];
#pragma unroll
        for (int ii = 0; ii < 4; ii++) wv[ii] = S[(r + 32 * ii) * 129 + j];
#pragma unroll
        for (int jj = 0; jj < 8; jj++) vv[jj] = Vs[j * 65 + c + 8 * jj];
#pragma unroll
        for (int ii = 0; ii < 4; ii++)
#pragma unroll
            for (int jj = 0; jj < 8; jj++)
                oacc[ii][jj] = fmaf(wv[ii], vv[jj], oacc[ii][jj]);
    }
#pragma unroll
    for (int ii = 0; ii < 4; ii++) {
        int i = r + 32 * ii;
#pragma unroll
        for (int jj = 0; jj < 8; jj++) {
            int hd = c + 8 * jj;
            size_t g = (size_t)(i * 8 + b) * 1024 + h * 64 + hd;
            float v = oacc[ii][jj];
            __nv_bfloat16 hb = __float2bfloat16(v);
            float res = v - __bfloat162float(hb);
            g_AOh[g] = hb;
            g_AOl[g] = __float2bfloat16(res);
        }
    }
}

// ---------------------------------------------------------------------------
extern "C" void kernel_launch(void* const* d_in, const int* in_sizes, int n_in,
                              void* d_out, int out_size) {
    const float* query = (const float*)d_in[0];
    const float* rel_pe = (const float*)d_in[1];
    const float* Wq = (const float*)d_in[3];
    const float* Wk = (const float*)d_in[4];
    const float* Wv = (const float*)d_in[5];
    const float* Wr = (const float*)d_in[6];
    const float* Wo = (const float*)d_in[7];
    const float* spk_emb = (const float*)d_in[8];
    const int* spk_mask = (const int*)d_in[10];
    float* out = (float*)d_out;

    cudaFuncSetAttribute(attn_kernel, cudaFuncAttributeMaxDynamicSharedMemorySize,
                         ATTN_SMEM_BYTES);
    cudaFuncSetAttribute(gemm_mid, cudaFuncAttributeMaxDynamicSharedMemorySize,
                         GEMM_SMEM_BYTES);
    cudaFuncSetAttribute(gemm_out, cudaFuncAttributeMaxDynamicSharedMemorySize,
                         GEMM_SMEM_BYTES);

    split_ghat<<<dim3(1024, 6), 256>>>(query, Wq, Wk, Wv, Wo, Wr, spk_emb);
    gemm_mid<<<dim3(16, 8, 5), 256, GEMM_SMEM_BYTES>>>(spk_emb, rel_pe);
    attn_kernel<<<dim3(8, 16), 256, ATTN_SMEM_BYTES>>>(spk_mask, spk_emb);
    gemm_out<<<dim3(16, 8), 256, GEMM_SMEM_BYTES>>>(out);
}

// round 9
// speedup vs baseline: 3.3389x; 1.0236x over previous
#include <cuda_runtime.h>
#include <cuda_bf16.h>
#include <cstdint>

#define Dm 1024
#define NELEM (Dm * Dm)

// fp32 scratch
__device__ float g_Cq[NELEM];
__device__ float g_Ck[NELEM];
__device__ float g_Cv[NELEM];
__device__ float g_GhatT[16 * Dm];      // [hs][k]
__device__ float g_dpart[4][Dm * 16];   // k-chunk partials of d[rr][hs]
// bf16 hi/lo split scratch
__device__ __nv_bfloat16 g_Ah[NELEM], g_Al[NELEM];          // query
__device__ __nv_bfloat16 g_Wh[4 * NELEM], g_Wl[4 * NELEM];  // Wq,Wk,Wv,Wo
__device__ __nv_bfloat16 g_AOh[NELEM], g_AOl[NELEM];        // attention out

__device__ __forceinline__ void cp_async16(uint32_t s, const void* g) {
    asm volatile("cp.async.cg.shared.global [%0], [%1], 16;" :: "r"(s), "l"(g));
}
__device__ __forceinline__ uint32_t smem_u32(const void* p) {
    uint32_t a;
    asm("{ .reg .u64 t; cvta.to.shared.u64 t, %1; cvt.u32.u64 %0, t; }" : "=r"(a) : "l"(p));
    return a;
}
__device__ __forceinline__ void mma_bf16(float* c, uint32_t a0, uint32_t a1,
                                         uint32_t a2, uint32_t a3,
                                         uint32_t b0, uint32_t b1) {
    asm volatile(
        "mma.sync.aligned.m16n8k16.row.col.f32.bf16.bf16.f32 "
        "{%0,%1,%2,%3}, {%4,%5,%6,%7}, {%8,%9}, {%0,%1,%2,%3};"
        : "+f"(c[0]), "+f"(c[1]), "+f"(c[2]), "+f"(c[3])
        : "r"(a0), "r"(a1), "r"(a2), "r"(a3), "r"(b0), "r"(b1));
}

// ---------------------------------------------------------------------------
// split5 + ghat fused. grid (1024, 6) x 256.
// ---------------------------------------------------------------------------
__global__ __launch_bounds__(256) void split_ghat(const float* __restrict__ q,
                                                  const float* __restrict__ wq,
                                                  const float* __restrict__ wk,
                                                  const float* __restrict__ wv,
                                                  const float* __restrict__ wo,
                                                  const float* __restrict__ Wr,
                                                  const float* __restrict__ spk_emb) {
    const int arr = blockIdx.y;
    if (arr == 5) {
        if (blockIdx.x >= 128) return;
        __shared__ float part[128];
        const int kc = blockIdx.x & 7;
        const int hs = blockIdx.x >> 3;
        const int kk = threadIdx.x & 127;
        const int ch = threadIdx.x >> 7;
        const float* base = Wr + (size_t)(hs * 64 + ch * 32) * 1024 + kc * 128 + kk;
        float s = 0.f;
#pragma unroll
        for (int c2 = 0; c2 < 32; c2++)
            s = fmaf(base[(size_t)c2 * 1024], spk_emb[hs * 64 + ch * 32 + c2], s);
        if (ch) part[kk] = s;
        __syncthreads();
        if (!ch) g_GhatT[hs * 1024 + kc * 128 + kk] = s + part[kk];
        return;
    }
    const float* src = (arr == 0) ? q : (arr == 1) ? wq : (arr == 2) ? wk
                                     : (arr == 3) ? wv : wo;
    __nv_bfloat16* hi = (arr == 0) ? g_Ah : g_Wh + (size_t)(arr - 1) * NELEM;
    __nv_bfloat16* lo = (arr == 0) ? g_Al : g_Wl + (size_t)(arr - 1) * NELEM;
    const int idx = (blockIdx.x * 256 + threadIdx.x) * 4;
    float4 v = *(const float4*)(src + idx);
    float f[4] = {v.x, v.y, v.z, v.w};
    unsigned short hb[4], lb[4];
#pragma unroll
    for (int i = 0; i < 4; i++) {
        __nv_bfloat16 hv = __float2bfloat16(f[i]);
        float res = f[i] - __bfloat162float(hv);
        __nv_bfloat16 lv = __float2bfloat16(res);
        hb[i] = *(unsigned short*)&hv;
        lb[i] = *(unsigned short*)&lv;
    }
    *(ushort4*)(hi + idx) = make_ushort4(hb[0], hb[1], hb[2], hb[3]);
    *(ushort4*)(lo + idx) = make_ushort4(lb[0], lb[1], lb[2], lb[3]);
}

// ---------------------------------------------------------------------------
// bf16x3 GEMM core: BM=64, BN=64, BK=32, 128 threads (4 warps, 2x2 grid),
// warp tile 32x32. 40KB smem -> multiple CTAs/SM for latency hiding.
// ---------------------------------------------------------------------------
#define RPAD 40
#define A_T (64 * RPAD)     // 2560 bf16
#define B_T (64 * RPAD)
#define OF_AH0 0
#define OF_AH1 A_T
#define OF_AL0 (2 * A_T)
#define OF_AL1 (3 * A_T)
#define OF_BH0 (4 * A_T)
#define OF_BH1 (4 * A_T + B_T)
#define OF_BL0 (4 * A_T + 2 * B_T)
#define OF_BL1 (4 * A_T + 3 * B_T)
#define GEMM_SMEM_BYTES ((4 * A_T + 4 * B_T) * 2)   // 40960

__device__ __forceinline__ void gemm_core(const __nv_bfloat16* __restrict__ Ah,
                                          const __nv_bfloat16* __restrict__ Al,
                                          const __nv_bfloat16* __restrict__ Bh,
                                          const __nv_bfloat16* __restrict__ Bl,
                                          float* __restrict__ C,
                                          const float* __restrict__ bias,
                                          int m0, int n0) {
    extern __shared__ __nv_bfloat16 smb[];
    const uint32_t sb = smem_u32(smb);
    const uint32_t* smw = (const uint32_t*)smb;
    const int tid = threadIdx.x;
    const int wid = tid >> 5, lane = tid & 31;
    const int g = lane >> 2, tg = lane & 3;
    const int wm = wid >> 1, wn = wid & 1;   // 2x2 warp grid, 32x32 tiles

    float acc[2][4][4];
#pragma unroll
    for (int mt = 0; mt < 2; mt++)
#pragma unroll
        for (int nt = 0; nt < 4; nt++)
#pragma unroll
            for (int r = 0; r < 4; r++) acc[mt][nt][r] = 0.f;

    auto load_tiles = [&](int buf, int k0) {
        const uint32_t ah = sb + (buf ? OF_AH1 : OF_AH0) * 2;
        const uint32_t al = sb + (buf ? OF_AL1 : OF_AL0) * 2;
        const uint32_t bh = sb + (buf ? OF_BH1 : OF_BH0) * 2;
        const uint32_t bl = sb + (buf ? OF_BL1 : OF_BL0) * 2;
#pragma unroll
        for (int i = 0; i < 2; i++) {
            int qd = tid + i * 128;
            int row = qd >> 2, c16 = qd & 3;
            uint32_t off = (uint32_t)(row * RPAD + c16 * 8) * 2;
            const size_t gsrc = (size_t)row * 1024 + k0 + c16 * 8;
            cp_async16(ah + off, Ah + (size_t)m0 * 1024 + gsrc);
            cp_async16(al + off, Al + (size_t)m0 * 1024 + gsrc);
            cp_async16(bh + off, Bh + (size_t)n0 * 1024 + gsrc);
            cp_async16(bl + off, Bl + (size_t)n0 * 1024 + gsrc);
        }
        asm volatile("cp.async.commit_group;");
    };

    load_tiles(0, 0);

    for (int it = 0; it < 32; ++it) {
        const int cur = it & 1;
        if (it + 1 < 32) {
            load_tiles(cur ^ 1, (it + 1) * 32);
            asm volatile("cp.async.wait_group 1;");
        } else {
            asm volatile("cp.async.wait_group 0;");
        }
        __syncthreads();

        const uint32_t wAH = (cur ? OF_AH1 : OF_AH0) / 2;
        const uint32_t wAL = (cur ? OF_AL1 : OF_AL0) / 2;
        const uint32_t wBH = (cur ? OF_BH1 : OF_BH0) / 2;
        const uint32_t wBL = (cur ? OF_BL1 : OF_BL0) / 2;
#pragma unroll
        for (int kk = 0; kk < 2; kk++) {
            const int kw = kk * 8;
            uint32_t ah[2][4], al[2][4];
#pragma unroll
            for (int mt = 0; mt < 2; mt++) {
                const int r0 = wm * 32 + mt * 16 + g;
                const uint32_t w0 = (uint32_t)r0 * 20 + kw + tg;
                const uint32_t w1 = (uint32_t)(r0 + 8) * 20 + kw + tg;
                ah[mt][0] = smw[wAH + w0];
                ah[mt][1] = smw[wAH + w1];
                ah[mt][2] = smw[wAH + w0 + 4];
                ah[mt][3] = smw[wAH + w1 + 4];
                al[mt][0] = smw[wAL + w0];
                al[mt][1] = smw[wAL + w1];
                al[mt][2] = smw[wAL + w0 + 4];
                al[mt][3] = smw[wAL + w1 + 4];
            }
#pragma unroll
            for (int nt = 0; nt < 4; nt++) {
                const int c0 = wn * 32 + nt * 8 + g;
                const uint32_t w0 = (uint32_t)c0 * 20 + kw + tg;
                uint32_t bh0 = smw[wBH + w0], bh1 = smw[wBH + w0 + 4];
                uint32_t bl0 = smw[wBL + w0], bl1 = smw[wBL + w0 + 4];
#pragma unroll
                for (int mt = 0; mt < 2; mt++) {
                    mma_bf16(acc[mt][nt], ah[mt][0], ah[mt][1], ah[mt][2], ah[mt][3],
                             bh0, bh1);
                    mma_bf16(acc[mt][nt], ah[mt][0], ah[mt][1], ah[mt][2], ah[mt][3],
                             bl0, bl1);
                    mma_bf16(acc[mt][nt], al[mt][0], al[mt][1], al[mt][2], al[mt][3],
                             bh0, bh1);
                }
            }
        }
        __syncthreads();
    }

#pragma unroll
    for (int mt = 0; mt < 2; mt++) {
        const int r0 = m0 + wm * 32 + mt * 16 + g;
#pragma unroll
        for (int nt = 0; nt < 4; nt++) {
            const int col = n0 + wn * 32 + nt * 8 + tg * 2;
            float bx = 0.f, by = 0.f;
            if (bias) {
                bx = bias[col];
                by = bias[col + 1];
            }
            float2 v0 = make_float2(acc[mt][nt][0] + bx, acc[mt][nt][1] + by);
            float2 v1 = make_float2(acc[mt][nt][2] + bx, acc[mt][nt][3] + by);
            *(float2*)(C + (size_t)r0 * 1024 + col) = v0;
            *(float2*)(C + (size_t)(r0 + 8) * 1024 + col) = v1;
        }
    }
}

// ---------------------------------------------------------------------------
// Fused mid kernel, grid (16, 16, 4) x 128:
//   z in [0,3): QKV GEMMs (m0 = y*64, n0 = x*64)
//   z == 3: dmat partials (256 logical blocks; each thread does 2 rr rows
//           sharing one GhatT stream)
// ---------------------------------------------------------------------------
__global__ __launch_bounds__(128) void gemm_mid(const float* __restrict__ spk_emb,
                                                const float* __restrict__ relpe) {
    const int z = blockIdx.z;
    if (z < 3) {
        const __nv_bfloat16* Bh = g_Wh + (size_t)z * NELEM;
        const __nv_bfloat16* Bl = g_Wl + (size_t)z * NELEM;
        float* C = (z == 0) ? g_Cq : (z == 1) ? g_Ck : g_Cv;
        const float* bias = (z == 0) ? spk_emb : nullptr;
        gemm_core(g_Ah, g_Al, Bh, Bl, C, bias, blockIdx.y * 64, blockIdx.x * 64);
        return;
    }
    const int f = blockIdx.y * 16 + blockIdx.x;       // 0..255
    const int chunk = f & 3;
    const int rrbase = (f >> 2) * 16;
    const int hs = threadIdx.x & 15;
    const int rr0 = rrbase + (threadIdx.x >> 4);      // 8 rows; +8 for second
    const int k0 = chunk * 256;
    const float4* arow0 = (const float4*)(relpe + (size_t)rr0 * 1024 + k0);
    const float4* arow1 = (const float4*)(relpe + (size_t)(rr0 + 8) * 1024 + k0);
    const float4* grow = (const float4*)(g_GhatT + (size_t)hs * 1024 + k0);
    float a0 = 0.f, a1 = 0.f, b0 = 0.f, b1 = 0.f;
#pragma unroll 8
    for (int k4 = 0; k4 < 64; k4++) {
        float4 gv = grow[k4];
        float4 x = arow0[k4];
        float4 y = arow1[k4];
        a0 = fmaf(x.x, gv.x, a0);
        a1 = fmaf(x.y, gv.y, a1);
        a0 = fmaf(x.z, gv.z, a0);
        a1 = fmaf(x.w, gv.w, a1);
        b0 = fmaf(y.x, gv.x, b0);
        b1 = fmaf(y.y, gv.y, b1);
        b0 = fmaf(y.z, gv.z, b0);
        b1 = fmaf(y.w, gv.w, b1);
    }
    g_dpart[chunk][rr0 * 16 + hs] = a0 + a1;
    g_dpart[chunk][(rr0 + 8) * 16 + hs] = b0 + b1;
}

__global__ __launch_bounds__(128) void gemm_out(float* __restrict__ out) {
    gemm_core(g_AOh, g_AOl, g_Wh + (size_t)3 * NELEM, g_Wl + (size_t)3 * NELEM,
              out, nullptr, blockIdx.y * 64, blockIdx.x * 64);
}

// ---------------------------------------------------------------------------
// Fused attention per (b, h). Output written as bf16 hi/lo (feeds gemm_out).
// ---------------------------------------------------------------------------
#define QS_OFF 0
#define KS_OFF 8320
#define VS_OFF 16640
#define S_OFF 24960
#define E0_OFF 41472
#define E1_OFF 41536
#define CV_OFF 41600
#define SD0_OFF 41728
#define SD1_OFF 41856
#define ATTN_SMEM_FLOATS 41984
#define ATTN_SMEM_BYTES (ATTN_SMEM_FLOATS * 4)

__global__ __launch_bounds__(256) void attn_kernel(const int* __restrict__ spk_mask,
                                                   const float* __restrict__ spk_emb) {
    extern __shared__ float sm[];
    float* Qs = sm + QS_OFF;
    float* Ks = sm + KS_OFF;
    float* Vs = sm + VS_OFF;
    float* S = sm + S_OFF;
    float* e0h = sm + E0_OFF;
    float* e1h = sm + E1_OFF;
    float* cvec = sm + CV_OFF;
    float* sd0 = sm + SD0_OFF;
    float* sd1 = sm + SD1_OFF;

    const int b = blockIdx.x, h = blockIdx.y;
    const int tid = threadIdx.x;

    for (int idx = tid; idx < 128 * 64; idx += 256) {
        int i = idx >> 6, hd = idx & 63;
        size_t g = (size_t)(i * 8 + b) * 1024 + h * 64 + hd;
        Qs[i * 65 + hd] = g_Cq[g];
        Ks[i * 65 + hd] = g_Ck[g];
        Vs[i * 65 + hd] = g_Cv[g];
    }
    if (tid < 64) {
        e0h[tid] = spk_emb[h * 64 + tid];
        e1h[tid] = spk_emb[1024 + h * 64 + tid];
    } else if (tid < 192) {
        int j = tid - 64;
        int off = (j * 8 + b) * 16 + h;
        cvec[j] = (g_dpart[0][off] + g_dpart[1][off]) +
                  (g_dpart[2][off] + g_dpart[3][off]);
    }
    __syncthreads();

    if (tid < 128) {
        float s0 = 0.f, s1 = 0.f;
        const float* qrow = Qs + tid * 65;
#pragma unroll
        for (int k = 0; k < 64; k++) {
            float q = qrow[k];
            s0 = fmaf(q, e0h[k], s0);
            s1 = fmaf(q, e1h[k], s1);
        }
        sd0[tid] = s0;
        sd1[tid] = s1;
    }
    __syncthreads();

    const int ti = tid >> 4, tj = tid & 15;
    float acc[8][8];
#pragma unroll
    for (int a = 0; a < 8; a++)
#pragma unroll
        for (int c2 = 0; c2 < 8; c2++) acc[a][c2] = 0.f;
    for (int k = 0; k < 64; k++) {
        float qa[8], kb[8];
#pragma unroll
        for (int ii = 0; ii < 8; ii++) qa[ii] = Qs[(ti + 16 * ii) * 65 + k];
#pragma unroll
        for (int jj = 0; jj < 8; jj++) kb[jj] = Ks[(tj + 16 * jj) * 65 + k];
#pragma unroll
        for (int ii = 0; ii < 8; ii++)
#pragma unroll
            for (int jj = 0; jj < 8; jj++)
                acc[ii][jj] = fmaf(qa[ii], kb[jj], acc[ii][jj]);
    }
    const int* spm = spk_mask + b * 128 * 128;
#pragma unroll
    for (int ii = 0; ii < 8; ii++) {
        int i = ti + 16 * ii;
#pragma unroll
        for (int jj = 0; jj < 8; jj++) {
            int j = tj + 16 * jj;
            float v;
            if (j <= i) {
                float a2 = spm[i * 128 + j] ? sd1[i] : sd0[i];
                float a3 = cvec[127 - i + j];
                v = (acc[ii][jj] + a2 + a3) * 0.125f;
            } else {
                v = 1e-30f;
            }
            S[i * 129 + j] = v;
        }
    }
    __syncthreads();

    if (tid < 128) {
        float* row = S + tid * 129;
        float mx = row[0];
        for (int j = 1; j < 128; j++) mx = fmaxf(mx, row[j]);
        float sum = 0.f;
        for (int j = 0; j < 128; j++) {
            float e = __expf(row[j] - mx);
            row[j] = e;
            sum += e;
        }
        float inv = 1.f / sum;
        for (int j = 0; j < 128; j++) row[j] *= inv;
    }
    __syncthreads();

    const int r = tid >> 3, c = tid & 7;
    float oacc[4][8];
#pragma unroll
    for (int a = 0; a < 4; a++)
#pragma unroll
        for (int c2 = 0; c2 < 8; c2++) oacc[a][c2] = 0.f;
    for (int j = 0; j < 128; j++) {
        float wv[4], vv[8];
#pragma unroll
        for (int ii = 0; ii < 4; ii++) wv[ii] = S[(r + 32 * ii) * 129 + j];
#pragma unroll
        for (int jj = 0; jj < 8; jj++) vv[jj] = Vs[j * 65 + c + 8 * jj];
#pragma unroll
        for (int ii = 0; ii < 4; ii++)
#pragma unroll
            for (int jj = 0; jj < 8; jj++)
                oacc[ii][jj] = fmaf(wv[ii], vv[jj], oacc[ii][jj]);
    }
#pragma unroll
    for (int ii = 0; ii < 4; ii++) {
        int i = r + 32 * ii;
#pragma unroll
        for (int jj = 0; jj < 8; jj++) {
            int hd = c + 8 * jj;
            size_t g = (size_t)(i * 8 + b) * 1024 + h * 64 + hd;
            float v = oacc[ii][jj];
            __nv_bfloat16 hb = __float2bfloat16(v);
            float res = v - __bfloat162float(hb);
            g_AOh[g] = hb;
            g_AOl[g] = __float2bfloat16(res);
        }
    }
}

// ---------------------------------------------------------------------------
extern "C" void kernel_launch(void* const* d_in, const int* in_sizes, int n_in,
                              void* d_out, int out_size) {
    const float* query = (const float*)d_in[0];
    const float* rel_pe = (const float*)d_in[1];
    const float* Wq = (const float*)d_in[3];
    const float* Wk = (const float*)d_in[4];
    const float* Wv = (const float*)d_in[5];
    const float* Wr = (const float*)d_in[6];
    const float* Wo = (const float*)d_in[7];
    const float* spk_emb = (const float*)d_in[8];
    const int* spk_mask = (const int*)d_in[10];
    float* out = (float*)d_out;

    cudaFuncSetAttribute(attn_kernel, cudaFuncAttributeMaxDynamicSharedMemorySize,
                         ATTN_SMEM_BYTES);
    cudaFuncSetAttribute(gemm_mid, cudaFuncAttributeMaxDynamicSharedMemorySize,
                         GEMM_SMEM_BYTES);
    cudaFuncSetAttribute(gemm_out, cudaFuncAttributeMaxDynamicSharedMemorySize,
                         GEMM_SMEM_BYTES);

    split_ghat<<<dim3(1024, 6), 256>>>(query, Wq, Wk, Wv, Wo, Wr, spk_emb);
    gemm_mid<<<dim3(16, 16, 4), 128, GEMM_SMEM_BYTES>>>(spk_emb, rel_pe);
    attn_kernel<<<dim3(8, 16), 256, ATTN_SMEM_BYTES>>>(spk_mask, spk_emb);
    gemm_out<<<dim3(16, 16), 128, GEMM_SMEM_BYTES>>>(out);
}